// round 10
// baseline (speedup 1.0000x reference)
#include <cuda_runtime.h>
#include <cuda_bf16.h>
#include <math.h>
#include <stdint.h>

#define BATCH 4
#define SEQL 2048
#define DMODEL 2048
#define NHEADS 16
#define DKH 128
#define MROWS (BATCH*SEQL)   // 8192

// ---------------- scratch (static device globals; no allocs allowed) ----------------
static __device__ float g_Q[BATCH*NHEADS*SEQL*DKH];     // [B,H,S,dk] fp32
static __device__ float g_K[BATCH*NHEADS*SEQL*DKH];
static __device__ float g_V[BATCH*NHEADS*SEQL*DKH];
static __device__ float g_ctx[BATCH*SEQL*DMODEL];       // attention output fp32
static __device__ float g_cos[SEQL*(DKH/2)];
static __device__ float g_sin[SEQL*(DKH/2)];
// hi/lo bf16 split operands (x and ctx share g_xhi/g_xlo: x dead after QKV)
static __device__ __nv_bfloat16 g_xhi[MROWS*DMODEL];
static __device__ __nv_bfloat16 g_xlo[MROWS*DMODEL];
static __device__ __nv_bfloat16 g_wqhi[DMODEL*DMODEL];
static __device__ __nv_bfloat16 g_wqlo[DMODEL*DMODEL];
static __device__ __nv_bfloat16 g_wkhi[DMODEL*DMODEL];
static __device__ __nv_bfloat16 g_wklo[DMODEL*DMODEL];
static __device__ __nv_bfloat16 g_wvhi[DMODEL*DMODEL];
static __device__ __nv_bfloat16 g_wvlo[DMODEL*DMODEL];
static __device__ __nv_bfloat16 g_wohi[DMODEL*DMODEL];
static __device__ __nv_bfloat16 g_wolo[DMODEL*DMODEL];

// ---------------- helpers ----------------
__device__ __forceinline__ uint32_t smem_u32(const void* p) {
    uint32_t a;
    asm("{ .reg .u64 t; cvta.to.shared.u64 t, %1; cvt.u32.u64 %0, t; }" : "=r"(a) : "l"(p));
    return a;
}
__device__ __forceinline__ void ldsm_x4(uint32_t* r, uint32_t addr) {
    asm volatile("ldmatrix.sync.aligned.m8n8.x4.shared.b16 {%0,%1,%2,%3}, [%4];"
        : "=r"(r[0]), "=r"(r[1]), "=r"(r[2]), "=r"(r[3]) : "r"(addr));
}
__device__ __forceinline__ void ldsm_x4_t(uint32_t* r, uint32_t addr) {
    asm volatile("ldmatrix.sync.aligned.m8n8.x4.trans.shared.b16 {%0,%1,%2,%3}, [%4];"
        : "=r"(r[0]), "=r"(r[1]), "=r"(r[2]), "=r"(r[3]) : "r"(addr));
}
__device__ __forceinline__ void ldsm_x2(uint32_t* r, uint32_t addr) {
    asm volatile("ldmatrix.sync.aligned.m8n8.x2.shared.b16 {%0,%1}, [%2];"
        : "=r"(r[0]), "=r"(r[1]) : "r"(addr));
}
__device__ __forceinline__ void mma16816(float* d, const uint32_t* a, const uint32_t* b) {
    asm volatile("mma.sync.aligned.m16n8k16.row.col.f32.bf16.bf16.f32 "
        "{%0,%1,%2,%3}, {%4,%5,%6,%7}, {%8,%9}, {%0,%1,%2,%3};"
        : "+f"(d[0]), "+f"(d[1]), "+f"(d[2]), "+f"(d[3])
        : "r"(a[0]), "r"(a[1]), "r"(a[2]), "r"(a[3]), "r"(b[0]), "r"(b[1]));
}
__device__ __forceinline__ uint32_t pack_hilo2(float x, float y,
                                               __nv_bfloat16& hx, __nv_bfloat16& hy) {
    hx = __float2bfloat16(x); hy = __float2bfloat16(y);
    __nv_bfloat162 p = __halves2bfloat162(hx, hy);
    return *(uint32_t*)&p;
}
__device__ __forceinline__ void split8(float4 a, float4 b, uint4& hi, uint4& lo) {
    float f[8] = {a.x, a.y, a.z, a.w, b.x, b.y, b.z, b.w};
    uint32_t hw[4], lw[4];
    #pragma unroll
    for (int i = 0; i < 4; i++) {
        __nv_bfloat16 h1, h2;
        hw[i] = pack_hilo2(f[2*i], f[2*i+1], h1, h2);
        __nv_bfloat16 t1, t2;
        lw[i] = pack_hilo2(f[2*i]   - __bfloat162float(h1),
                           f[2*i+1] - __bfloat162float(h2), t1, t2);
    }
    hi = make_uint4(hw[0], hw[1], hw[2], hw[3]);
    lo = make_uint4(lw[0], lw[1], lw[2], lw[3]);
}
__device__ __forceinline__ uint32_t swb(uint32_t regionB, int row, int col) {
    return regionB + (uint32_t)(row * 256) + (uint32_t)(((((col) >> 3) ^ (row & 7)) << 4));
}

// ---------------- RoPE table init ----------------
__global__ void init_tables_kernel()
{
    int t = blockIdx.x;
    int i = threadIdx.x;
    double freq = exp(-(double)i * (log(10000.0) / 64.0));
    float ang = (float)t * (float)freq;
    g_cos[t*64 + i] = (float)cos((double)ang);
    g_sin[t*64 + i] = (float)sin((double)ang);
}

// ---------------- fp32 -> (hi, lo) bf16 split ----------------
__global__ void convert_hilo_kernel(const float* __restrict__ src, int which, int n4)
{
    int idx = blockIdx.x * blockDim.x + threadIdx.x;
    if (idx >= n4) return;
    const float* s = src ? src : g_ctx;
    __nv_bfloat16 *hi, *lo;
    switch (which) {
        case 1: hi = g_wqhi; lo = g_wqlo; break;
        case 2: hi = g_wkhi; lo = g_wklo; break;
        case 3: hi = g_wvhi; lo = g_wvlo; break;
        case 4: hi = g_wohi; lo = g_wolo; break;
        default: hi = g_xhi; lo = g_xlo; break;   // 0 and 5
    }
    float4 v = ((const float4*)s)[idx];
    __nv_bfloat16 h0 = __float2bfloat16(v.x);
    __nv_bfloat16 h1 = __float2bfloat16(v.y);
    __nv_bfloat16 h2 = __float2bfloat16(v.z);
    __nv_bfloat16 h3 = __float2bfloat16(v.w);
    __nv_bfloat16 l0 = __float2bfloat16(v.x - __bfloat162float(h0));
    __nv_bfloat16 l1 = __float2bfloat16(v.y - __bfloat162float(h1));
    __nv_bfloat16 l2 = __float2bfloat16(v.z - __bfloat162float(h2));
    __nv_bfloat16 l3 = __float2bfloat16(v.w - __bfloat162float(h3));
    __nv_bfloat162* hp = (__nv_bfloat162*)hi;
    __nv_bfloat162* lp = (__nv_bfloat162*)lo;
    hp[2*idx]   = __halves2bfloat162(h0, h1);
    hp[2*idx+1] = __halves2bfloat162(h2, h3);
    lp[2*idx]   = __halves2bfloat162(l0, l1);
    lp[2*idx+1] = __halves2bfloat162(l2, l3);
}

// ---------------- mma.sync bf16 hi/lo GEMM, register-prefetch double buffer ----------------
// 128x128 tile/CTA, KC=32, 2 stages x 40KB DYNAMIC smem (80KB — proven size; no cp.async).
// Schedule per chunk c: [LDG c+2 in flight] sync; mma(stage c&1); STS chunk c+1 -> stage
// (c+1)&1; LDG chunk c+2 -> regs. One barrier per chunk; write-target stage is never
// concurrently read (all threads passed the previous barrier after finishing it).
// mode 0: A=ctx(xhi/xlo), write Cp fp32 row-major
// mode 1/2: A=x, +RoPE (+1/sqrt(dk) for Q), write g_Q / g_K fp32
// mode 3: A=x, plain, write g_V fp32
#define KC 32
#define STR 40
#define REG_B (128*STR*2)          // 10240 bytes per region
#define STAGE_B (4*REG_B)          // 40960 bytes per stage
#define GEMM_SMEM (2*STAGE_B)      // 81920 bytes

__global__ void __launch_bounds__(256, 2) ms_gemm_kernel(float* __restrict__ Cp, int mode,
                                                         const int* __restrict__ tokpos)
{
    extern __shared__ __nv_bfloat16 dsm[];
    const uint32_t sdyn = smem_u32(dsm);

    const int tid = threadIdx.x;
    const int wid = tid >> 5, lane = tid & 31;
    const int wm = wid >> 2, wn = wid & 3;
    const int bm = blockIdx.y * 128, bn = blockIdx.x * 128;

    const __nv_bfloat16 *Ah = g_xhi, *Al = g_xlo, *Bh, *Bl;
    if (mode == 0)      { Bh = g_wohi; Bl = g_wolo; }
    else if (mode == 1) { Bh = g_wqhi; Bl = g_wqlo; }
    else if (mode == 2) { Bh = g_wkhi; Bl = g_wklo; }
    else                { Bh = g_wvhi; Bl = g_wvlo; }

    float acc[4][4][4];
    #pragma unroll
    for (int i = 0; i < 4; i++)
        #pragma unroll
        for (int j = 0; j < 4; j++)
            #pragma unroll
            for (int d = 0; d < 4; d++) acc[i][j][d] = 0.f;

    const int r8 = lane & 7, sel = lane >> 3;
    const int a_row_part = wm*64 + r8 + (sel & 1) * 8;
    const int a_col_part = (sel >> 1) * 8;
    const int b_row_part = wn*32 + r8;
    const int b_col_part = (sel & 1) * 8;

    // loader slots: row0 in [0,64), row1 = row0+64; seg in [0,4) (8 bf16 per seg)
    const int lrow0 = tid >> 2, lseg = tid & 3;
    const size_t ga0 = (size_t)(bm + lrow0) * DMODEL + lseg*8;
    const size_t gb0 = (size_t)(bn + lrow0) * DMODEL + lseg*8;
    const size_t ga1 = (size_t)(bm + lrow0 + 64) * DMODEL + lseg*8;
    const size_t gb1 = (size_t)(bn + lrow0 + 64) * DMODEL + lseg*8;
    const uint32_t so0 = (uint32_t)(lrow0*STR + lseg*8) * 2u;
    const uint32_t so1 = (uint32_t)((lrow0 + 64)*STR + lseg*8) * 2u;

    uint4 pa0h, pa0l, pb0h, pb0l, pa1h, pa1l, pb1h, pb1l;

    #define LOADG(cc) do {                                   \
        const int _k0 = (cc) * KC;                           \
        pa0h = *(const uint4*)(Ah + ga0 + _k0);              \
        pa0l = *(const uint4*)(Al + ga0 + _k0);              \
        pb0h = *(const uint4*)(Bh + gb0 + _k0);              \
        pb0l = *(const uint4*)(Bl + gb0 + _k0);              \
        pa1h = *(const uint4*)(Ah + ga1 + _k0);              \
        pa1l = *(const uint4*)(Al + ga1 + _k0);              \
        pb1h = *(const uint4*)(Bh + gb1 + _k0);              \
        pb1l = *(const uint4*)(Bl + gb1 + _k0);              \
    } while (0)

    #define STORE_STAGE(sidx) do {                                     \
        char* _s = (char*)dsm + (sidx) * STAGE_B;                      \
        *(uint4*)(_s + 0*REG_B + so0) = pa0h;                          \
        *(uint4*)(_s + 1*REG_B + so0) = pa0l;                          \
        *(uint4*)(_s + 2*REG_B + so0) = pb0h;                          \
        *(uint4*)(_s + 3*REG_B + so0) = pb0l;                          \
        *(uint4*)(_s + 0*REG_B + so1) = pa1h;                          \
        *(uint4*)(_s + 1*REG_B + so1) = pa1l;                          \
        *(uint4*)(_s + 2*REG_B + so1) = pb1h;                          \
        *(uint4*)(_s + 3*REG_B + so1) = pb1l;                          \
    } while (0)

    LOADG(0);
    STORE_STAGE(0);
    LOADG(1);

    for (int c = 0; c < 64; c++) {
        __syncthreads();                      // stage c&1 fully stored by all threads

        const uint32_t sb0 = sdyn + (uint32_t)(c & 1) * STAGE_B;
        const uint32_t sah = sb0, sal = sb0 + REG_B;
        const uint32_t sbh = sb0 + 2*REG_B, sbl = sb0 + 3*REG_B;
        #pragma unroll
        for (int kk = 0; kk < 2; kk++) {
            const int kof = kk * 16;
            uint32_t bfh[4][2], bfl[4][2];
            #pragma unroll
            for (int an = 0; an < 4; an++) {
                const uint32_t ba = 2u * (uint32_t)((b_row_part + an*8)*STR + b_col_part + kof);
                ldsm_x2(bfh[an], sbh + ba);
                ldsm_x2(bfl[an], sbl + ba);
            }
            #pragma unroll
            for (int am = 0; am < 4; am++) {
                const uint32_t aa = 2u * (uint32_t)((a_row_part + am*16)*STR + a_col_part + kof);
                uint32_t afh[4], afl[4];
                ldsm_x4(afh, sah + aa);
                ldsm_x4(afl, sal + aa);
                #pragma unroll
                for (int an = 0; an < 4; an++) {
                    mma16816(acc[am][an], afh, bfh[an]);
                    mma16816(acc[am][an], afh, bfl[an]);
                    mma16816(acc[am][an], afl, bfh[an]);
                }
            }
        }

        if (c < 63) STORE_STAGE((c + 1) & 1); // chunk c+1 -> other stage (safe: see header)
        if (c < 62) LOADG(c + 2);             // prefetch; latency hidden behind next mma
    }

    const int rr = lane >> 2;
    const int cc = (lane & 3) * 2;
    if (mode == 0) {
        #pragma unroll
        for (int am = 0; am < 4; am++)
            #pragma unroll
            for (int h2 = 0; h2 < 2; h2++) {
                const int m = bm + wm*64 + am*16 + rr + h2*8;
                #pragma unroll
                for (int an = 0; an < 4; an++) {
                    const int n = bn + wn*32 + an*8 + cc;
                    *(float2*)(Cp + (size_t)m * DMODEL + n) =
                        make_float2(acc[am][an][h2*2], acc[am][an][h2*2+1]);
                }
            }
    } else {
        const int h = bn >> 7;
        float* base = (mode == 1) ? g_Q : ((mode == 2) ? g_K : g_V);
        const float qscale = 0.08838834764831845f;  // 1/sqrt(128)
        #pragma unroll
        for (int am = 0; am < 4; am++)
            #pragma unroll
            for (int h2 = 0; h2 < 2; h2++) {
                const int m = bm + wm*64 + am*16 + rr + h2*8;
                const int b = m >> 11;
                const int s = m & (SEQL - 1);
                float* drow = base + ((size_t)(b * NHEADS + h) * SEQL + s) * DKH;
                if (mode == 3) {
                    #pragma unroll
                    for (int an = 0; an < 4; an++) {
                        const int d = wn*32 + an*8 + cc;
                        *(float2*)(drow + d) =
                            make_float2(acc[am][an][h2*2], acc[am][an][h2*2+1]);
                    }
                } else {
                    const int p = tokpos[s];
                    #pragma unroll
                    for (int an = 0; an < 4; an++) {
                        const int d = wn*32 + an*8 + cc;
                        const int pi = d >> 1;
                        const float co = g_cos[p*64 + pi];
                        const float si = g_sin[p*64 + pi];
                        const float x1 = acc[am][an][h2*2];
                        const float x2 = acc[am][an][h2*2+1];
                        float r1 = co*x1 - si*x2;
                        float r2 = si*x1 + co*x2;
                        if (mode == 1) { r1 *= qscale; r2 *= qscale; }
                        *(float2*)(drow + d) = make_float2(r1, r2);
                    }
                }
            }
    }
}

// ---------------- flash attention via mma.sync bf16 hi/lo (R7-proven, 96KB smem) ----------------
#define QH_B 0u
#define QL_B 32768u
#define KH_B 65536u
#define KL_B 73728u
#define VH_B 81920u
#define VL_B 90112u
#define ASM_BYTES 98304

__global__ void __launch_bounds__(256) mha_mma_kernel()
{
    extern __shared__ char sbc[];
    const uint32_t sbase = smem_u32(sbc);
    const int tid = threadIdx.x, wid = tid >> 5, lane = tid & 31;
    const int qi = (int)gridDim.x - 1 - (int)blockIdx.x;   // big q-tiles first
    const int bh = blockIdx.y;
    const int q0 = qi * 128;
    const size_t boff = (size_t)bh * SEQL * DKH;
    const float* Qb = g_Q + boff;
    const float* Kb = g_K + boff;
    const float* Vb = g_V + boff;

    for (int idx = tid; idx < 128*16; idx += 256) {
        const int row = idx >> 4, chunk = idx & 15;
        const float* src = Qb + (size_t)(q0 + row) * DKH + chunk * 8;
        float4 a = *(const float4*)src;
        float4 b = *(const float4*)(src + 4);
        uint4 hi, lo;
        split8(a, b, hi, lo);
        const uint32_t off = (uint32_t)(row * 256) + (uint32_t)(((chunk ^ (row & 7)) << 4));
        *(uint4*)(sbc + QH_B + off) = hi;
        *(uint4*)(sbc + QL_B + off) = lo;
    }

    const int r8 = lane & 7, sel = lane >> 3;
    const int qrow = wid*16 + r8 + ((sel & 1) << 3);
    const int qcolb = (sel >> 1) << 3;
    const int krow_b = r8 + ((sel >> 1) << 3);
    const int kcolb = (sel & 1) << 3;
    const int vrow_b = r8 + ((sel & 1) << 3);
    const int vcolb = (sel >> 1) << 3;

    const int rr = lane >> 2, cc2 = (lane & 3) * 2;
    const int rw0 = q0 + wid * 16;
    float m0 = -INFINITY, m1 = -INFINITY, l0 = 0.f, l1 = 0.f;
    float oacc[16][4];
    #pragma unroll
    for (int i = 0; i < 16; i++)
        #pragma unroll
        for (int j = 0; j < 4; j++) oacc[i][j] = 0.f;

    const int nkt = 4 * qi + 4;
    for (int kt = 0; kt < nkt; kt++) {
        const int k0g = kt * 32;
        __syncthreads();
        for (int idx = tid; idx < 1024; idx += 256) {
            const int which = idx >> 9;
            const int rem = idx & 511;
            const int row = rem >> 4, chunk = rem & 15;
            const float* src = (which ? Vb : Kb) + (size_t)(k0g + row) * DKH + chunk * 8;
            float4 a = *(const float4*)src;
            float4 b = *(const float4*)(src + 4);
            uint4 hi, lo;
            split8(a, b, hi, lo);
            const uint32_t off = (uint32_t)(row * 256) + (uint32_t)(((chunk ^ (row & 7)) << 4));
            const uint32_t hB = which ? VH_B : KH_B;
            const uint32_t lB = which ? VL_B : KL_B;
            *(uint4*)(sbc + hB + off) = hi;
            *(uint4*)(sbc + lB + off) = lo;
        }
        __syncthreads();

        if (k0g <= rw0 + 15) {
            float sacc[4][4];
            #pragma unroll
            for (int j = 0; j < 4; j++)
                #pragma unroll
                for (int d = 0; d < 4; d++) sacc[j][d] = 0.f;
            #pragma unroll
            for (int kk = 0; kk < 8; kk++) {
                uint32_t afh[4], afl[4];
                ldsm_x4(afh, sbase + swb(QH_B, qrow, qcolb + kk*16));
                ldsm_x4(afl, sbase + swb(QL_B, qrow, qcolb + kk*16));
                #pragma unroll
                for (int np = 0; np < 2; np++) {
                    uint32_t bh4[4], bl4[4];
                    ldsm_x4(bh4, sbase + swb(KH_B, krow_b + np*16, kcolb + kk*16));
                    ldsm_x4(bl4, sbase + swb(KL_B, krow_b + np*16, kcolb + kk*16));
                    mma16816(sacc[2*np],   afh, bh4);
                    mma16816(sacc[2*np],   afh, bl4);
                    mma16816(sacc[2*np],   afl, bh4);
                    mma16816(sacc[2*np+1], afh, bh4+2);
                    mma16816(sacc[2*np+1], afh, bl4+2);
                    mma16816(sacc[2*np+1], afl, bh4+2);
                }
            }
            if (k0g + 31 > rw0) {
                const int row0 = rw0 + rr, row1 = row0 + 8;
                #pragma unroll
                for (int j = 0; j < 4; j++) {
                    const int c0 = k0g + j*8 + cc2;
                    if (c0     > row0) sacc[j][0] = -1e30f;
                    if (c0 + 1 > row0) sacc[j][1] = -1e30f;
                    if (c0     > row1) sacc[j][2] = -1e30f;
                    if (c0 + 1 > row1) sacc[j][3] = -1e30f;
                }
            }
            float mt0 = -INFINITY, mt1 = -INFINITY;
            #pragma unroll
            for (int j = 0; j < 4; j++) {
                mt0 = fmaxf(mt0, fmaxf(sacc[j][0], sacc[j][1]));
                mt1 = fmaxf(mt1, fmaxf(sacc[j][2], sacc[j][3]));
            }
            mt0 = fmaxf(mt0, __shfl_xor_sync(0xffffffffu, mt0, 1));
            mt0 = fmaxf(mt0, __shfl_xor_sync(0xffffffffu, mt0, 2));
            mt1 = fmaxf(mt1, __shfl_xor_sync(0xffffffffu, mt1, 1));
            mt1 = fmaxf(mt1, __shfl_xor_sync(0xffffffffu, mt1, 2));
            const float mn0 = fmaxf(m0, mt0), mn1 = fmaxf(m1, mt1);
            const float al0 = __expf(m0 - mn0), al1 = __expf(m1 - mn1);
            m0 = mn0; m1 = mn1;
            float s0 = 0.f, s1 = 0.f;
            uint32_t pah[2][4], pal[2][4];
            #pragma unroll
            for (int j = 0; j < 4; j++) {
                const float p00 = __expf(sacc[j][0] - m0);
                const float p01 = __expf(sacc[j][1] - m0);
                const float p10 = __expf(sacc[j][2] - m1);
                const float p11 = __expf(sacc[j][3] - m1);
                s0 += p00 + p01; s1 += p10 + p11;
                __nv_bfloat16 h00, h01, h10, h11;
                const uint32_t ph0 = pack_hilo2(p00, p01, h00, h01);
                const uint32_t ph1 = pack_hilo2(p10, p11, h10, h11);
                __nv_bfloat16 tt0, tt1;
                const uint32_t pl0 = pack_hilo2(p00 - __bfloat162float(h00),
                                                p01 - __bfloat162float(h01), tt0, tt1);
                const uint32_t pl1 = pack_hilo2(p10 - __bfloat162float(h10),
                                                p11 - __bfloat162float(h11), tt0, tt1);
                const int t = j >> 1, u = (j & 1) * 2;
                pah[t][u]   = ph0; pah[t][u+1] = ph1;
                pal[t][u]   = pl0; pal[t][u+1] = pl1;
            }
            s0 += __shfl_xor_sync(0xffffffffu, s0, 1);
            s0 += __shfl_xor_sync(0xffffffffu, s0, 2);
            s1 += __shfl_xor_sync(0xffffffffu, s1, 1);
            s1 += __shfl_xor_sync(0xffffffffu, s1, 2);
            l0 = l0*al0 + s0; l1 = l1*al1 + s1;
            #pragma unroll
            for (int na = 0; na < 16; na++) {
                oacc[na][0] *= al0; oacc[na][1] *= al0;
                oacc[na][2] *= al1; oacc[na][3] *= al1;
            }
            #pragma unroll
            for (int t = 0; t < 2; t++) {
                #pragma unroll
                for (int np = 0; np < 8; np++) {
                    uint32_t vh4[4], vl4[4];
                    ldsm_x4_t(vh4, sbase + swb(VH_B, vrow_b + t*16, vcolb + np*16));
                    ldsm_x4_t(vl4, sbase + swb(VL_B, vrow_b + t*16, vcolb + np*16));
                    mma16816(oacc[2*np],   pah[t], vh4);
                    mma16816(oacc[2*np],   pah[t], vl4);
                    mma16816(oacc[2*np],   pal[t], vh4);
                    mma16816(oacc[2*np+1], pah[t], vh4+2);
                    mma16816(oacc[2*np+1], pah[t], vl4+2);
                    mma16816(oacc[2*np+1], pal[t], vh4+2);
                }
            }
        }
    }

    const float inv0 = 1.f / l0, inv1 = 1.f / l1;
    const int brow = bh >> 4, hh = bh & 15;
    const int s0r = rw0 + rr, s1r = s0r + 8;
    float* d0 = g_ctx + ((size_t)(brow*SEQL + s0r))*DMODEL + hh*DKH + cc2;
    float* d1 = g_ctx + ((size_t)(brow*SEQL + s1r))*DMODEL + hh*DKH + cc2;
    #pragma unroll
    for (int na = 0; na < 16; na++) {
        *(float2*)(d0 + na*8) = make_float2(oacc[na][0]*inv0, oacc[na][1]*inv0);
        *(float2*)(d1 + na*8) = make_float2(oacc[na][2]*inv1, oacc[na][3]*inv1);
    }
}

// ---------------- launch ----------------
extern "C" void kernel_launch(void* const* d_in, const int* in_sizes, int n_in,
                              void* d_out, int out_size)
{
    (void)in_sizes; (void)n_in; (void)out_size;
    const float* x      = (const float*)d_in[0];
    const int*   tokpos = (const int*)d_in[1];
    const float* Wq     = (const float*)d_in[2];
    const float* Wk     = (const float*)d_in[3];
    const float* Wv     = (const float*)d_in[4];
    const float* Wo     = (const float*)d_in[5];
    float* out = (float*)d_out;

    init_tables_kernel<<<SEQL, 64>>>();

    const int n4x = MROWS * DMODEL / 4;
    const int n4w = DMODEL * DMODEL / 4;
    convert_hilo_kernel<<<n4x/256, 256>>>(x,  0, n4x);
    convert_hilo_kernel<<<n4w/256, 256>>>(Wq, 1, n4w);
    convert_hilo_kernel<<<n4w/256, 256>>>(Wk, 2, n4w);
    convert_hilo_kernel<<<n4w/256, 256>>>(Wv, 3, n4w);
    convert_hilo_kernel<<<n4w/256, 256>>>(Wo, 4, n4w);

    cudaFuncSetAttribute(ms_gemm_kernel, cudaFuncAttributeMaxDynamicSharedMemorySize, GEMM_SMEM);
    dim3 gg(DMODEL / 128, MROWS / 128);
    ms_gemm_kernel<<<gg, 256, GEMM_SMEM>>>(nullptr, 1, tokpos);   // Q (+RoPE, +scale)
    ms_gemm_kernel<<<gg, 256, GEMM_SMEM>>>(nullptr, 2, tokpos);   // K (+RoPE)
    ms_gemm_kernel<<<gg, 256, GEMM_SMEM>>>(nullptr, 3, tokpos);   // V

    cudaFuncSetAttribute(mha_mma_kernel, cudaFuncAttributeMaxDynamicSharedMemorySize, ASM_BYTES);
    mha_mma_kernel<<<dim3(SEQL/128, BATCH*NHEADS), 256, ASM_BYTES>>>();

    convert_hilo_kernel<<<n4x/256, 256>>>(nullptr, 5, n4x);       // ctx -> xhi/xlo
    ms_gemm_kernel<<<gg, 256, GEMM_SMEM>>>(out, 0, nullptr);      // output projection
}

// round 13
// speedup vs baseline: 1.0360x; 1.0360x over previous
#include <cuda_runtime.h>
#include <cuda_bf16.h>
#include <math.h>
#include <stdint.h>

#define BATCH 4
#define SEQL 2048
#define DMODEL 2048
#define NHEADS 16
#define DKH 128
#define MROWS (BATCH*SEQL)   // 8192

// ---------------- scratch (static device globals; no allocs allowed) ----------------
static __device__ float g_Q[BATCH*NHEADS*SEQL*DKH];     // [B,H,S,dk] fp32
static __device__ float g_K[BATCH*NHEADS*SEQL*DKH];
static __device__ float g_V[BATCH*NHEADS*SEQL*DKH];
static __device__ float g_ctx[BATCH*SEQL*DMODEL];       // attention output fp32
static __device__ float g_cos[SEQL*(DKH/2)];
static __device__ float g_sin[SEQL*(DKH/2)];
// hi/lo bf16 split operands (x and ctx share g_xhi/g_xlo: x dead after QKV)
static __device__ __nv_bfloat16 g_xhi[MROWS*DMODEL];
static __device__ __nv_bfloat16 g_xlo[MROWS*DMODEL];
static __device__ __nv_bfloat16 g_wqhi[DMODEL*DMODEL];
static __device__ __nv_bfloat16 g_wqlo[DMODEL*DMODEL];
static __device__ __nv_bfloat16 g_wkhi[DMODEL*DMODEL];
static __device__ __nv_bfloat16 g_wklo[DMODEL*DMODEL];
static __device__ __nv_bfloat16 g_wvhi[DMODEL*DMODEL];
static __device__ __nv_bfloat16 g_wvlo[DMODEL*DMODEL];
static __device__ __nv_bfloat16 g_wohi[DMODEL*DMODEL];
static __device__ __nv_bfloat16 g_wolo[DMODEL*DMODEL];

// ---------------- helpers ----------------
__device__ __forceinline__ uint32_t smem_u32(const void* p) {
    uint32_t a;
    asm("{ .reg .u64 t; cvta.to.shared.u64 t, %1; cvt.u32.u64 %0, t; }" : "=r"(a) : "l"(p));
    return a;
}
__device__ __forceinline__ void ldsm_x4(uint32_t* r, uint32_t addr) {
    asm volatile("ldmatrix.sync.aligned.m8n8.x4.shared.b16 {%0,%1,%2,%3}, [%4];"
        : "=r"(r[0]), "=r"(r[1]), "=r"(r[2]), "=r"(r[3]) : "r"(addr));
}
__device__ __forceinline__ void ldsm_x4_t(uint32_t* r, uint32_t addr) {
    asm volatile("ldmatrix.sync.aligned.m8n8.x4.trans.shared.b16 {%0,%1,%2,%3}, [%4];"
        : "=r"(r[0]), "=r"(r[1]), "=r"(r[2]), "=r"(r[3]) : "r"(addr));
}
__device__ __forceinline__ void ldsm_x2(uint32_t* r, uint32_t addr) {
    asm volatile("ldmatrix.sync.aligned.m8n8.x2.shared.b16 {%0,%1}, [%2];"
        : "=r"(r[0]), "=r"(r[1]) : "r"(addr));
}
__device__ __forceinline__ void mma16816(float* d, const uint32_t* a, const uint32_t* b) {
    asm volatile("mma.sync.aligned.m16n8k16.row.col.f32.bf16.bf16.f32 "
        "{%0,%1,%2,%3}, {%4,%5,%6,%7}, {%8,%9}, {%0,%1,%2,%3};"
        : "+f"(d[0]), "+f"(d[1]), "+f"(d[2]), "+f"(d[3])
        : "r"(a[0]), "r"(a[1]), "r"(a[2]), "r"(a[3]), "r"(b[0]), "r"(b[1]));
}
__device__ __forceinline__ uint32_t pack_hilo2(float x, float y,
                                               __nv_bfloat16& hx, __nv_bfloat16& hy) {
    hx = __float2bfloat16(x); hy = __float2bfloat16(y);
    __nv_bfloat162 p = __halves2bfloat162(hx, hy);
    return *(uint32_t*)&p;
}
__device__ __forceinline__ void split8(float4 a, float4 b, uint4& hi, uint4& lo) {
    float f[8] = {a.x, a.y, a.z, a.w, b.x, b.y, b.z, b.w};
    uint32_t hw[4], lw[4];
    #pragma unroll
    for (int i = 0; i < 4; i++) {
        __nv_bfloat16 h1, h2;
        hw[i] = pack_hilo2(f[2*i], f[2*i+1], h1, h2);
        __nv_bfloat16 t1, t2;
        lw[i] = pack_hilo2(f[2*i]   - __bfloat162float(h1),
                           f[2*i+1] - __bfloat162float(h2), t1, t2);
    }
    hi = make_uint4(hw[0], hw[1], hw[2], hw[3]);
    lo = make_uint4(lw[0], lw[1], lw[2], lw[3]);
}
__device__ __forceinline__ uint32_t swb(uint32_t regionB, int row, int col) {
    return regionB + (uint32_t)(row * 256) + (uint32_t)(((((col) >> 3) ^ (row & 7)) << 4));
}

// ---------------- RoPE table init ----------------
__global__ void init_tables_kernel()
{
    int t = blockIdx.x;
    int i = threadIdx.x;
    double freq = exp(-(double)i * (log(10000.0) / 64.0));
    float ang = (float)t * (float)freq;
    g_cos[t*64 + i] = (float)cos((double)ang);
    g_sin[t*64 + i] = (float)sin((double)ang);
}

// ---------------- fp32 -> (hi, lo) bf16 split ----------------
__global__ void convert_hilo_kernel(const float* __restrict__ src, int which, int n4)
{
    int idx = blockIdx.x * blockDim.x + threadIdx.x;
    if (idx >= n4) return;
    const float* s = src ? src : g_ctx;
    __nv_bfloat16 *hi, *lo;
    switch (which) {
        case 1: hi = g_wqhi; lo = g_wqlo; break;
        case 2: hi = g_wkhi; lo = g_wklo; break;
        case 3: hi = g_wvhi; lo = g_wvlo; break;
        case 4: hi = g_wohi; lo = g_wolo; break;
        default: hi = g_xhi; lo = g_xlo; break;   // 0 and 5
    }
    float4 v = ((const float4*)s)[idx];
    __nv_bfloat16 h0 = __float2bfloat16(v.x);
    __nv_bfloat16 h1 = __float2bfloat16(v.y);
    __nv_bfloat16 h2 = __float2bfloat16(v.z);
    __nv_bfloat16 h3 = __float2bfloat16(v.w);
    __nv_bfloat16 l0 = __float2bfloat16(v.x - __bfloat162float(h0));
    __nv_bfloat16 l1 = __float2bfloat16(v.y - __bfloat162float(h1));
    __nv_bfloat16 l2 = __float2bfloat16(v.z - __bfloat162float(h2));
    __nv_bfloat16 l3 = __float2bfloat16(v.w - __bfloat162float(h3));
    __nv_bfloat162* hp = (__nv_bfloat162*)hi;
    __nv_bfloat162* lp = (__nv_bfloat162*)lo;
    hp[2*idx]   = __halves2bfloat162(h0, h1);
    hp[2*idx+1] = __halves2bfloat162(h2, h3);
    lp[2*idx]   = __halves2bfloat162(l0, l1);
    lp[2*idx+1] = __halves2bfloat162(l2, l3);
}

// ---------------- mma.sync bf16 hi/lo GEMM (R7-proven body; fused-QKV grid) ----------------
// mode 9: fused QKV — one launch, grid.y in [0,192): operator = y>>6 (0:Q,1:K,2:V),
//         row-block = y&63. Epilogues IDENTICAL to the proven per-mode fp32 ones.
// mode 0: A=ctx(xhi/xlo), write Cp fp32 row-major
#define KC 32
#define STR 40

__global__ void __launch_bounds__(256, 2) ms_gemm_kernel(float* __restrict__ Cp, int mode,
                                                         const int* __restrict__ tokpos)
{
    __shared__ __nv_bfloat16 sAh[128*STR];
    __shared__ __nv_bfloat16 sAl[128*STR];
    __shared__ __nv_bfloat16 sBh[128*STR];
    __shared__ __nv_bfloat16 sBl[128*STR];

    int emode, bmBlk;
    if (mode == 9) { emode = 1 + (int)(blockIdx.y >> 6); bmBlk = (int)(blockIdx.y & 63); }
    else           { emode = mode;                        bmBlk = (int)blockIdx.y; }

    const int tid = threadIdx.x;
    const int wid = tid >> 5, lane = tid & 31;
    const int wm = wid >> 2, wn = wid & 3;
    const int bm = bmBlk * 128, bn = blockIdx.x * 128;

    const __nv_bfloat16 *Ah = g_xhi, *Al = g_xlo, *Bh, *Bl;
    if (emode == 0)      { Bh = g_wohi; Bl = g_wolo; }
    else if (emode == 1) { Bh = g_wqhi; Bl = g_wqlo; }
    else if (emode == 2) { Bh = g_wkhi; Bl = g_wklo; }
    else                 { Bh = g_wvhi; Bl = g_wvlo; }

    float acc[4][4][4];
    #pragma unroll
    for (int i = 0; i < 4; i++)
        #pragma unroll
        for (int j = 0; j < 4; j++)
            #pragma unroll
            for (int d = 0; d < 4; d++) acc[i][j][d] = 0.f;

    const uint32_t sah = smem_u32(sAh), sal = smem_u32(sAl);
    const uint32_t sbh = smem_u32(sBh), sbl = smem_u32(sBl);
    const int r8 = lane & 7, sel = lane >> 3;
    const int a_row_part = wm*64 + r8 + (sel & 1) * 8;
    const int a_col_part = (sel >> 1) * 8;
    const int b_row_part = wn*32 + r8;
    const int b_col_part = (sel & 1) * 8;

    for (int c = 0; c < 64; c++) {
        const int k0 = c * KC;
        __syncthreads();
        #pragma unroll
        for (int t = 0; t < 2; t++) {
            const int slot = tid + t*256;
            const int row = slot >> 2, seg = slot & 3;
            const int so = row*STR + seg*8;
            const size_t ga = (size_t)(bm + row) * DMODEL + k0 + seg*8;
            const size_t gb = (size_t)(bn + row) * DMODEL + k0 + seg*8;
            *(uint4*)(sAh + so) = *(const uint4*)(Ah + ga);
            *(uint4*)(sAl + so) = *(const uint4*)(Al + ga);
            *(uint4*)(sBh + so) = *(const uint4*)(Bh + gb);
            *(uint4*)(sBl + so) = *(const uint4*)(Bl + gb);
        }
        __syncthreads();
        #pragma unroll
        for (int kk = 0; kk < 2; kk++) {
            const int kof = kk * 16;
            uint32_t bfh[4][2], bfl[4][2];
            #pragma unroll
            for (int an = 0; an < 4; an++) {
                const uint32_t ba = 2u * (uint32_t)((b_row_part + an*8)*STR + b_col_part + kof);
                ldsm_x2(bfh[an], sbh + ba);
                ldsm_x2(bfl[an], sbl + ba);
            }
            #pragma unroll
            for (int am = 0; am < 4; am++) {
                const uint32_t aa = 2u * (uint32_t)((a_row_part + am*16)*STR + a_col_part + kof);
                uint32_t afh[4], afl[4];
                ldsm_x4(afh, sah + aa);
                ldsm_x4(afl, sal + aa);
                #pragma unroll
                for (int an = 0; an < 4; an++) {
                    mma16816(acc[am][an], afh, bfh[an]);
                    mma16816(acc[am][an], afh, bfl[an]);
                    mma16816(acc[am][an], afl, bfh[an]);
                }
            }
        }
    }

    const int rr = lane >> 2;
    const int cc = (lane & 3) * 2;
    if (emode == 0) {
        #pragma unroll
        for (int am = 0; am < 4; am++)
            #pragma unroll
            for (int h2 = 0; h2 < 2; h2++) {
                const int m = bm + wm*64 + am*16 + rr + h2*8;
                #pragma unroll
                for (int an = 0; an < 4; an++) {
                    const int n = bn + wn*32 + an*8 + cc;
                    *(float2*)(Cp + (size_t)m * DMODEL + n) =
                        make_float2(acc[am][an][h2*2], acc[am][an][h2*2+1]);
                }
            }
    } else {
        const int h = bn >> 7;
        float* base = (emode == 1) ? g_Q : ((emode == 2) ? g_K : g_V);
        const float qscale = 0.08838834764831845f;  // 1/sqrt(128)
        #pragma unroll
        for (int am = 0; am < 4; am++)
            #pragma unroll
            for (int h2 = 0; h2 < 2; h2++) {
                const int m = bm + wm*64 + am*16 + rr + h2*8;
                const int b = m >> 11;
                const int s = m & (SEQL - 1);
                float* drow = base + ((size_t)(b * NHEADS + h) * SEQL + s) * DKH;
                if (emode == 3) {
                    #pragma unroll
                    for (int an = 0; an < 4; an++) {
                        const int d = wn*32 + an*8 + cc;
                        *(float2*)(drow + d) =
                            make_float2(acc[am][an][h2*2], acc[am][an][h2*2+1]);
                    }
                } else {
                    const int p = tokpos[s];
                    #pragma unroll
                    for (int an = 0; an < 4; an++) {
                        const int d = wn*32 + an*8 + cc;
                        const int pi = d >> 1;
                        const float co = g_cos[p*64 + pi];
                        const float si = g_sin[p*64 + pi];
                        const float x1 = acc[am][an][h2*2];
                        const float x2 = acc[am][an][h2*2+1];
                        float r1 = co*x1 - si*x2;
                        float r2 = si*x1 + co*x2;
                        if (emode == 1) { r1 *= qscale; r2 *= qscale; }
                        *(float2*)(drow + d) = make_float2(r1, r2);
                    }
                }
            }
    }
}

// ---------------- flash attention via mma.sync bf16 hi/lo (R7-proven, 96KB smem) ----------------
#define QH_B 0u
#define QL_B 32768u
#define KH_B 65536u
#define KL_B 73728u
#define VH_B 81920u
#define VL_B 90112u
#define ASM_BYTES 98304

__global__ void __launch_bounds__(256) mha_mma_kernel()
{
    extern __shared__ char sbc[];
    const uint32_t sbase = smem_u32(sbc);
    const int tid = threadIdx.x, wid = tid >> 5, lane = tid & 31;
    const int qi = (int)gridDim.x - 1 - (int)blockIdx.x;   // big q-tiles first
    const int bh = blockIdx.y;
    const int q0 = qi * 128;
    const size_t boff = (size_t)bh * SEQL * DKH;
    const float* Qb = g_Q + boff;
    const float* Kb = g_K + boff;
    const float* Vb = g_V + boff;

    // stage Q (fp32 -> hi/lo, swizzled)
    for (int idx = tid; idx < 128*16; idx += 256) {
        const int row = idx >> 4, chunk = idx & 15;
        const float* src = Qb + (size_t)(q0 + row) * DKH + chunk * 8;
        float4 a = *(const float4*)src;
        float4 b = *(const float4*)(src + 4);
        uint4 hi, lo;
        split8(a, b, hi, lo);
        const uint32_t off = (uint32_t)(row * 256) + (uint32_t)(((chunk ^ (row & 7)) << 4));
        *(uint4*)(sbc + QH_B + off) = hi;
        *(uint4*)(sbc + QL_B + off) = lo;
    }

    const int r8 = lane & 7, sel = lane >> 3;
    const int qrow = wid*16 + r8 + ((sel & 1) << 3);
    const int qcolb = (sel >> 1) << 3;
    const int krow_b = r8 + ((sel >> 1) << 3);
    const int kcolb = (sel & 1) << 3;
    const int vrow_b = r8 + ((sel & 1) << 3);
    const int vcolb = (sel >> 1) << 3;

    const int rr = lane >> 2, cc2 = (lane & 3) * 2;
    const int rw0 = q0 + wid * 16;
    float m0 = -INFINITY, m1 = -INFINITY, l0 = 0.f, l1 = 0.f;
    float oacc[16][4];
    #pragma unroll
    for (int i = 0; i < 16; i++)
        #pragma unroll
        for (int j = 0; j < 4; j++) oacc[i][j] = 0.f;

    const int nkt = 4 * qi + 4;
    for (int kt = 0; kt < nkt; kt++) {
        const int k0g = kt * 32;
        __syncthreads();
        // stage K,V tile (32 rows each, fp32 -> hi/lo, swizzled)
        for (int idx = tid; idx < 1024; idx += 256) {
            const int which = idx >> 9;            // 0: K, 1: V
            const int rem = idx & 511;
            const int row = rem >> 4, chunk = rem & 15;
            const float* src = (which ? Vb : Kb) + (size_t)(k0g + row) * DKH + chunk * 8;
            float4 a = *(const float4*)src;
            float4 b = *(const float4*)(src + 4);
            uint4 hi, lo;
            split8(a, b, hi, lo);
            const uint32_t off = (uint32_t)(row * 256) + (uint32_t)(((chunk ^ (row & 7)) << 4));
            const uint32_t hB = which ? VH_B : KH_B;
            const uint32_t lB = which ? VL_B : KL_B;
            *(uint4*)(sbc + hB + off) = hi;
            *(uint4*)(sbc + lB + off) = lo;
        }
        __syncthreads();

        if (k0g <= rw0 + 15) {                 // warp-tile not fully masked
            float sacc[4][4];
            #pragma unroll
            for (int j = 0; j < 4; j++)
                #pragma unroll
                for (int d = 0; d < 4; d++) sacc[j][d] = 0.f;
            #pragma unroll
            for (int kk = 0; kk < 8; kk++) {
                uint32_t afh[4], afl[4];
                ldsm_x4(afh, sbase + swb(QH_B, qrow, qcolb + kk*16));
                ldsm_x4(afl, sbase + swb(QL_B, qrow, qcolb + kk*16));
                #pragma unroll
                for (int np = 0; np < 2; np++) {
                    uint32_t bh4[4], bl4[4];
                    ldsm_x4(bh4, sbase + swb(KH_B, krow_b + np*16, kcolb + kk*16));
                    ldsm_x4(bl4, sbase + swb(KL_B, krow_b + np*16, kcolb + kk*16));
                    mma16816(sacc[2*np],   afh, bh4);
                    mma16816(sacc[2*np],   afh, bl4);
                    mma16816(sacc[2*np],   afl, bh4);
                    mma16816(sacc[2*np+1], afh, bh4+2);
                    mma16816(sacc[2*np+1], afh, bl4+2);
                    mma16816(sacc[2*np+1], afl, bh4+2);
                }
            }
            if (k0g + 31 > rw0) {
                const int row0 = rw0 + rr, row1 = row0 + 8;
                #pragma unroll
                for (int j = 0; j < 4; j++) {
                    const int c0 = k0g + j*8 + cc2;
                    if (c0     > row0) sacc[j][0] = -1e30f;
                    if (c0 + 1 > row0) sacc[j][1] = -1e30f;
                    if (c0     > row1) sacc[j][2] = -1e30f;
                    if (c0 + 1 > row1) sacc[j][3] = -1e30f;
                }
            }
            float mt0 = -INFINITY, mt1 = -INFINITY;
            #pragma unroll
            for (int j = 0; j < 4; j++) {
                mt0 = fmaxf(mt0, fmaxf(sacc[j][0], sacc[j][1]));
                mt1 = fmaxf(mt1, fmaxf(sacc[j][2], sacc[j][3]));
            }
            mt0 = fmaxf(mt0, __shfl_xor_sync(0xffffffffu, mt0, 1));
            mt0 = fmaxf(mt0, __shfl_xor_sync(0xffffffffu, mt0, 2));
            mt1 = fmaxf(mt1, __shfl_xor_sync(0xffffffffu, mt1, 1));
            mt1 = fmaxf(mt1, __shfl_xor_sync(0xffffffffu, mt1, 2));
            const float mn0 = fmaxf(m0, mt0), mn1 = fmaxf(m1, mt1);
            const float al0 = __expf(m0 - mn0), al1 = __expf(m1 - mn1);
            m0 = mn0; m1 = mn1;
            float s0 = 0.f, s1 = 0.f;
            uint32_t pah[2][4], pal[2][4];
            #pragma unroll
            for (int j = 0; j < 4; j++) {
                const float p00 = __expf(sacc[j][0] - m0);
                const float p01 = __expf(sacc[j][1] - m0);
                const float p10 = __expf(sacc[j][2] - m1);
                const float p11 = __expf(sacc[j][3] - m1);
                s0 += p00 + p01; s1 += p10 + p11;
                __nv_bfloat16 h00, h01, h10, h11;
                const uint32_t ph0 = pack_hilo2(p00, p01, h00, h01);
                const uint32_t ph1 = pack_hilo2(p10, p11, h10, h11);
                __nv_bfloat16 tt0, tt1;
                const uint32_t pl0 = pack_hilo2(p00 - __bfloat162float(h00),
                                                p01 - __bfloat162float(h01), tt0, tt1);
                const uint32_t pl1 = pack_hilo2(p10 - __bfloat162float(h10),
                                                p11 - __bfloat162float(h11), tt0, tt1);
                const int t = j >> 1, u = (j & 1) * 2;
                pah[t][u]   = ph0; pah[t][u+1] = ph1;
                pal[t][u]   = pl0; pal[t][u+1] = pl1;
            }
            s0 += __shfl_xor_sync(0xffffffffu, s0, 1);
            s0 += __shfl_xor_sync(0xffffffffu, s0, 2);
            s1 += __shfl_xor_sync(0xffffffffu, s1, 1);
            s1 += __shfl_xor_sync(0xffffffffu, s1, 2);
            l0 = l0*al0 + s0; l1 = l1*al1 + s1;
            #pragma unroll
            for (int na = 0; na < 16; na++) {
                oacc[na][0] *= al0; oacc[na][1] *= al0;
                oacc[na][2] *= al1; oacc[na][3] *= al1;
            }
            #pragma unroll
            for (int t = 0; t < 2; t++) {
                #pragma unroll
                for (int np = 0; np < 8; np++) {
                    uint32_t vh4[4], vl4[4];
                    ldsm_x4_t(vh4, sbase + swb(VH_B, vrow_b + t*16, vcolb + np*16));
                    ldsm_x4_t(vl4, sbase + swb(VL_B, vrow_b + t*16, vcolb + np*16));
                    mma16816(oacc[2*np],   pah[t], vh4);
                    mma16816(oacc[2*np],   pah[t], vl4);
                    mma16816(oacc[2*np],   pal[t], vh4);
                    mma16816(oacc[2*np+1], pah[t], vh4+2);
                    mma16816(oacc[2*np+1], pah[t], vl4+2);
                    mma16816(oacc[2*np+1], pal[t], vh4+2);
                }
            }
        }
    }

    // ---- epilogue: fp32 ctx ----
    const float inv0 = 1.f / l0, inv1 = 1.f / l1;
    const int brow = bh >> 4, hh = bh & 15;
    const int s0r = rw0 + rr, s1r = s0r + 8;
    float* d0 = g_ctx + ((size_t)(brow*SEQL + s0r))*DMODEL + hh*DKH + cc2;
    float* d1 = g_ctx + ((size_t)(brow*SEQL + s1r))*DMODEL + hh*DKH + cc2;
    #pragma unroll
    for (int na = 0; na < 16; na++) {
        *(float2*)(d0 + na*8) = make_float2(oacc[na][0]*inv0, oacc[na][1]*inv0);
        *(float2*)(d1 + na*8) = make_float2(oacc[na][2]*inv1, oacc[na][3]*inv1);
    }
}

// ---------------- launch ----------------
extern "C" void kernel_launch(void* const* d_in, const int* in_sizes, int n_in,
                              void* d_out, int out_size)
{
    (void)in_sizes; (void)n_in; (void)out_size;
    const float* x      = (const float*)d_in[0];
    const int*   tokpos = (const int*)d_in[1];
    const float* Wq     = (const float*)d_in[2];
    const float* Wk     = (const float*)d_in[3];
    const float* Wv     = (const float*)d_in[4];
    const float* Wo     = (const float*)d_in[5];
    float* out = (float*)d_out;

    init_tables_kernel<<<SEQL, 64>>>();

    const int n4x = MROWS * DMODEL / 4;
    const int n4w = DMODEL * DMODEL / 4;
    convert_hilo_kernel<<<n4x/256, 256>>>(x,  0, n4x);
    convert_hilo_kernel<<<n4w/256, 256>>>(Wq, 1, n4w);
    convert_hilo_kernel<<<n4w/256, 256>>>(Wk, 2, n4w);
    convert_hilo_kernel<<<n4w/256, 256>>>(Wv, 3, n4w);
    convert_hilo_kernel<<<n4w/256, 256>>>(Wo, 4, n4w);

    // fused QKV projection: one launch, grid.y = 3 * 64 row-blocks
    ms_gemm_kernel<<<dim3(DMODEL/128, 3*(MROWS/128)), 256>>>(nullptr, 9, tokpos);

    cudaFuncSetAttribute(mha_mma_kernel, cudaFuncAttributeMaxDynamicSharedMemorySize, ASM_BYTES);
    mha_mma_kernel<<<dim3(SEQL/128, BATCH*NHEADS), 256, ASM_BYTES>>>();

    convert_hilo_kernel<<<n4x/256, 256>>>(nullptr, 5, n4x);  // ctx -> xhi/xlo
    ms_gemm_kernel<<<dim3(DMODEL/128, MROWS/128), 256>>>(out, 0, nullptr);  // output proj
}

// round 15
// speedup vs baseline: 1.1305x; 1.0912x over previous
#include <cuda_runtime.h>
#include <cuda_bf16.h>
#include <math.h>
#include <stdint.h>

#define BATCH 4
#define SEQL 2048
#define DMODEL 2048
#define NHEADS 16
#define DKH 128
#define MROWS (BATCH*SEQL)   // 8192

// ---------------- scratch (static device globals; no allocs allowed) ----------------
static __device__ float g_Q[BATCH*NHEADS*SEQL*DKH];     // [B,H,S,dk] fp32
static __device__ float g_K[BATCH*NHEADS*SEQL*DKH];
static __device__ float g_V[BATCH*NHEADS*SEQL*DKH];
static __device__ float g_ctx[BATCH*SEQL*DMODEL];       // attention output fp32
static __device__ float g_cos[SEQL*(DKH/2)];
static __device__ float g_sin[SEQL*(DKH/2)];
// hi/lo bf16 split operands (x and ctx share g_xhi/g_xlo: x dead after QKV)
static __device__ __nv_bfloat16 g_xhi[MROWS*DMODEL];
static __device__ __nv_bfloat16 g_xlo[MROWS*DMODEL];
static __device__ __nv_bfloat16 g_wqhi[DMODEL*DMODEL];
static __device__ __nv_bfloat16 g_wqlo[DMODEL*DMODEL];
static __device__ __nv_bfloat16 g_wkhi[DMODEL*DMODEL];
static __device__ __nv_bfloat16 g_wklo[DMODEL*DMODEL];
static __device__ __nv_bfloat16 g_wvhi[DMODEL*DMODEL];
static __device__ __nv_bfloat16 g_wvlo[DMODEL*DMODEL];
static __device__ __nv_bfloat16 g_wohi[DMODEL*DMODEL];
static __device__ __nv_bfloat16 g_wolo[DMODEL*DMODEL];

// ---------------- helpers ----------------
__device__ __forceinline__ uint32_t smem_u32(const void* p) {
    uint32_t a;
    asm("{ .reg .u64 t; cvta.to.shared.u64 t, %1; cvt.u32.u64 %0, t; }" : "=r"(a) : "l"(p));
    return a;
}
__device__ __forceinline__ void ldsm_x4(uint32_t* r, uint32_t addr) {
    asm volatile("ldmatrix.sync.aligned.m8n8.x4.shared.b16 {%0,%1,%2,%3}, [%4];"
        : "=r"(r[0]), "=r"(r[1]), "=r"(r[2]), "=r"(r[3]) : "r"(addr));
}
__device__ __forceinline__ void ldsm_x4_t(uint32_t* r, uint32_t addr) {
    asm volatile("ldmatrix.sync.aligned.m8n8.x4.trans.shared.b16 {%0,%1,%2,%3}, [%4];"
        : "=r"(r[0]), "=r"(r[1]), "=r"(r[2]), "=r"(r[3]) : "r"(addr));
}
__device__ __forceinline__ void ldsm_x2(uint32_t* r, uint32_t addr) {
    asm volatile("ldmatrix.sync.aligned.m8n8.x2.shared.b16 {%0,%1}, [%2];"
        : "=r"(r[0]), "=r"(r[1]) : "r"(addr));
}
__device__ __forceinline__ void mma16816(float* d, const uint32_t* a, const uint32_t* b) {
    asm volatile("mma.sync.aligned.m16n8k16.row.col.f32.bf16.bf16.f32 "
        "{%0,%1,%2,%3}, {%4,%5,%6,%7}, {%8,%9}, {%0,%1,%2,%3};"
        : "+f"(d[0]), "+f"(d[1]), "+f"(d[2]), "+f"(d[3])
        : "r"(a[0]), "r"(a[1]), "r"(a[2]), "r"(a[3]), "r"(b[0]), "r"(b[1]));
}
__device__ __forceinline__ uint32_t pack_hilo2(float x, float y,
                                               __nv_bfloat16& hx, __nv_bfloat16& hy) {
    hx = __float2bfloat16(x); hy = __float2bfloat16(y);
    __nv_bfloat162 p = __halves2bfloat162(hx, hy);
    return *(uint32_t*)&p;
}
__device__ __forceinline__ void split8(float4 a, float4 b, uint4& hi, uint4& lo) {
    float f[8] = {a.x, a.y, a.z, a.w, b.x, b.y, b.z, b.w};
    uint32_t hw[4], lw[4];
    #pragma unroll
    for (int i = 0; i < 4; i++) {
        __nv_bfloat16 h1, h2;
        hw[i] = pack_hilo2(f[2*i], f[2*i+1], h1, h2);
        __nv_bfloat16 t1, t2;
        lw[i] = pack_hilo2(f[2*i]   - __bfloat162float(h1),
                           f[2*i+1] - __bfloat162float(h2), t1, t2);
    }
    hi = make_uint4(hw[0], hw[1], hw[2], hw[3]);
    lo = make_uint4(lw[0], lw[1], lw[2], lw[3]);
}
__device__ __forceinline__ uint32_t swb(uint32_t regionB, int row, int col) {
    return regionB + (uint32_t)(row * 256) + (uint32_t)(((((col) >> 3) ^ (row & 7)) << 4));
}

// ---------------- RoPE table init ----------------
__global__ void init_tables_kernel()
{
    int t = blockIdx.x;
    int i = threadIdx.x;
    double freq = exp(-(double)i * (log(10000.0) / 64.0));
    float ang = (float)t * (float)freq;
    g_cos[t*64 + i] = (float)cos((double)ang);
    g_sin[t*64 + i] = (float)sin((double)ang);
}

// ---------------- fp32 -> (hi, lo) bf16 split ----------------
__global__ void convert_hilo_kernel(const float* __restrict__ src, int which, int n4)
{
    int idx = blockIdx.x * blockDim.x + threadIdx.x;
    if (idx >= n4) return;
    const float* s = src ? src : g_ctx;
    __nv_bfloat16 *hi, *lo;
    switch (which) {
        case 1: hi = g_wqhi; lo = g_wqlo; break;
        case 2: hi = g_wkhi; lo = g_wklo; break;
        case 3: hi = g_wvhi; lo = g_wvlo; break;
        case 4: hi = g_wohi; lo = g_wolo; break;
        default: hi = g_xhi; lo = g_xlo; break;   // 0 and 5
    }
    float4 v = ((const float4*)s)[idx];
    __nv_bfloat16 h0 = __float2bfloat16(v.x);
    __nv_bfloat16 h1 = __float2bfloat16(v.y);
    __nv_bfloat16 h2 = __float2bfloat16(v.z);
    __nv_bfloat16 h3 = __float2bfloat16(v.w);
    __nv_bfloat16 l0 = __float2bfloat16(v.x - __bfloat162float(h0));
    __nv_bfloat16 l1 = __float2bfloat16(v.y - __bfloat162float(h1));
    __nv_bfloat16 l2 = __float2bfloat16(v.z - __bfloat162float(h2));
    __nv_bfloat16 l3 = __float2bfloat16(v.w - __bfloat162float(h3));
    __nv_bfloat162* hp = (__nv_bfloat162*)hi;
    __nv_bfloat162* lp = (__nv_bfloat162*)lo;
    hp[2*idx]   = __halves2bfloat162(h0, h1);
    hp[2*idx+1] = __halves2bfloat162(h2, h3);
    lp[2*idx]   = __halves2bfloat162(l0, l1);
    lp[2*idx+1] = __halves2bfloat162(l2, l3);
}

// ---------------- mma.sync bf16 hi/lo GEMM (R13 body; KC=64, dynamic smem) ----------------
// mode 9: fused QKV — one launch, grid.y in [0,192): operator = y>>6 (0:Q,1:K,2:V),
//         row-block = y&63. fp32 epilogues (proven path).
// mode 0: A=ctx(xhi/xlo), write Cp fp32 row-major
#define KC 64
#define STR 72                      // 64 + 8 pad (bf16) — same conflict-free class as 40
#define REGN (128*STR)              // elements per region
#define GEMM_SMEM (4*REGN*2)        // 73728 bytes dynamic (proven-size class: R10 ran 80KB)

__global__ void __launch_bounds__(256, 2) ms_gemm_kernel(float* __restrict__ Cp, int mode,
                                                         const int* __restrict__ tokpos)
{
    extern __shared__ __nv_bfloat16 dsm[];
    __nv_bfloat16* sAh = dsm;
    __nv_bfloat16* sAl = dsm + REGN;
    __nv_bfloat16* sBh = dsm + 2*REGN;
    __nv_bfloat16* sBl = dsm + 3*REGN;

    int emode, bmBlk;
    if (mode == 9) { emode = 1 + (int)(blockIdx.y >> 6); bmBlk = (int)(blockIdx.y & 63); }
    else           { emode = mode;                        bmBlk = (int)blockIdx.y; }

    const int tid = threadIdx.x;
    const int wid = tid >> 5, lane = tid & 31;
    const int wm = wid >> 2, wn = wid & 3;
    const int bm = bmBlk * 128, bn = blockIdx.x * 128;

    const __nv_bfloat16 *Ah = g_xhi, *Al = g_xlo, *Bh, *Bl;
    if (emode == 0)      { Bh = g_wohi; Bl = g_wolo; }
    else if (emode == 1) { Bh = g_wqhi; Bl = g_wqlo; }
    else if (emode == 2) { Bh = g_wkhi; Bl = g_wklo; }
    else                 { Bh = g_wvhi; Bl = g_wvlo; }

    float acc[4][4][4];
    #pragma unroll
    for (int i = 0; i < 4; i++)
        #pragma unroll
        for (int j = 0; j < 4; j++)
            #pragma unroll
            for (int d = 0; d < 4; d++) acc[i][j][d] = 0.f;

    const uint32_t sah = smem_u32(sAh), sal = smem_u32(sAl);
    const uint32_t sbh = smem_u32(sBh), sbl = smem_u32(sBl);
    const int r8 = lane & 7, sel = lane >> 3;
    const int a_row_part = wm*64 + r8 + (sel & 1) * 8;
    const int a_col_part = (sel >> 1) * 8;
    const int b_row_part = wn*32 + r8;
    const int b_col_part = (sel & 1) * 8;

    for (int c = 0; c < 32; c++) {            // 32 chunks of KC=64 (was 64 of 32)
        const int k0 = c * KC;
        __syncthreads();
        #pragma unroll
        for (int t = 0; t < 4; t++) {
            const int slot = tid + t*256;      // 0..1023
            const int row = slot >> 3, seg = slot & 7;
            const int so = row*STR + seg*8;
            const size_t ga = (size_t)(bm + row) * DMODEL + k0 + seg*8;
            const size_t gb = (size_t)(bn + row) * DMODEL + k0 + seg*8;
            *(uint4*)(sAh + so) = *(const uint4*)(Ah + ga);
            *(uint4*)(sAl + so) = *(const uint4*)(Al + ga);
            *(uint4*)(sBh + so) = *(const uint4*)(Bh + gb);
            *(uint4*)(sBl + so) = *(const uint4*)(Bl + gb);
        }
        __syncthreads();
        #pragma unroll
        for (int kk = 0; kk < 4; kk++) {       // 4 k-steps of 16 (was 2)
            const int kof = kk * 16;
            uint32_t bfh[4][2], bfl[4][2];
            #pragma unroll
            for (int an = 0; an < 4; an++) {
                const uint32_t ba = 2u * (uint32_t)((b_row_part + an*8)*STR + b_col_part + kof);
                ldsm_x2(bfh[an], sbh + ba);
                ldsm_x2(bfl[an], sbl + ba);
            }
            #pragma unroll
            for (int am = 0; am < 4; am++) {
                const uint32_t aa = 2u * (uint32_t)((a_row_part + am*16)*STR + a_col_part + kof);
                uint32_t afh[4], afl[4];
                ldsm_x4(afh, sah + aa);
                ldsm_x4(afl, sal + aa);
                #pragma unroll
                for (int an = 0; an < 4; an++) {
                    mma16816(acc[am][an], afh, bfh[an]);
                    mma16816(acc[am][an], afh, bfl[an]);
                    mma16816(acc[am][an], afl, bfh[an]);
                }
            }
        }
    }

    const int rr = lane >> 2;
    const int cc = (lane & 3) * 2;
    if (emode == 0) {
        #pragma unroll
        for (int am = 0; am < 4; am++)
            #pragma unroll
            for (int h2 = 0; h2 < 2; h2++) {
                const int m = bm + wm*64 + am*16 + rr + h2*8;
                #pragma unroll
                for (int an = 0; an < 4; an++) {
                    const int n = bn + wn*32 + an*8 + cc;
                    *(float2*)(Cp + (size_t)m * DMODEL + n) =
                        make_float2(acc[am][an][h2*2], acc[am][an][h2*2+1]);
                }
            }
    } else {
        const int h = bn >> 7;
        float* base = (emode == 1) ? g_Q : ((emode == 2) ? g_K : g_V);
        const float qscale = 0.08838834764831845f;  // 1/sqrt(128)
        #pragma unroll
        for (int am = 0; am < 4; am++)
            #pragma unroll
            for (int h2 = 0; h2 < 2; h2++) {
                const int m = bm + wm*64 + am*16 + rr + h2*8;
                const int b = m >> 11;
                const int s = m & (SEQL - 1);
                float* drow = base + ((size_t)(b * NHEADS + h) * SEQL + s) * DKH;
                if (emode == 3) {
                    #pragma unroll
                    for (int an = 0; an < 4; an++) {
                        const int d = wn*32 + an*8 + cc;
                        *(float2*)(drow + d) =
                            make_float2(acc[am][an][h2*2], acc[am][an][h2*2+1]);
                    }
                } else {
                    const int p = tokpos[s];
                    #pragma unroll
                    for (int an = 0; an < 4; an++) {
                        const int d = wn*32 + an*8 + cc;
                        const int pi = d >> 1;
                        const float co = g_cos[p*64 + pi];
                        const float si = g_sin[p*64 + pi];
                        const float x1 = acc[am][an][h2*2];
                        const float x2 = acc[am][an][h2*2+1];
                        float r1 = co*x1 - si*x2;
                        float r2 = si*x1 + co*x2;
                        if (emode == 1) { r1 *= qscale; r2 *= qscale; }
                        *(float2*)(drow + d) = make_float2(r1, r2);
                    }
                }
            }
    }
}

// ---------------- flash attention via mma.sync bf16 hi/lo (R13-proven, 96KB smem) ----------------
#define QH_B 0u
#define QL_B 32768u
#define KH_B 65536u
#define KL_B 73728u
#define VH_B 81920u
#define VL_B 90112u
#define ASM_BYTES 98304

__global__ void __launch_bounds__(256) mha_mma_kernel()
{
    extern __shared__ char sbc[];
    const uint32_t sbase = smem_u32(sbc);
    const int tid = threadIdx.x, wid = tid >> 5, lane = tid & 31;
    const int qi = (int)gridDim.x - 1 - (int)blockIdx.x;   // big q-tiles first
    const int bh = blockIdx.y;
    const int q0 = qi * 128;
    const size_t boff = (size_t)bh * SEQL * DKH;
    const float* Qb = g_Q + boff;
    const float* Kb = g_K + boff;
    const float* Vb = g_V + boff;

    // stage Q (fp32 -> hi/lo, swizzled)
    for (int idx = tid; idx < 128*16; idx += 256) {
        const int row = idx >> 4, chunk = idx & 15;
        const float* src = Qb + (size_t)(q0 + row) * DKH + chunk * 8;
        float4 a = *(const float4*)src;
        float4 b = *(const float4*)(src + 4);
        uint4 hi, lo;
        split8(a, b, hi, lo);
        const uint32_t off = (uint32_t)(row * 256) + (uint32_t)(((chunk ^ (row & 7)) << 4));
        *(uint4*)(sbc + QH_B + off) = hi;
        *(uint4*)(sbc + QL_B + off) = lo;
    }

    const int r8 = lane & 7, sel = lane >> 3;
    const int qrow = wid*16 + r8 + ((sel & 1) << 3);
    const int qcolb = (sel >> 1) << 3;
    const int krow_b = r8 + ((sel >> 1) << 3);
    const int kcolb = (sel & 1) << 3;
    const int vrow_b = r8 + ((sel & 1) << 3);
    const int vcolb = (sel >> 1) << 3;

    const int rr = lane >> 2, cc2 = (lane & 3) * 2;
    const int rw0 = q0 + wid * 16;
    float m0 = -INFINITY, m1 = -INFINITY, l0 = 0.f, l1 = 0.f;
    float oacc[16][4];
    #pragma unroll
    for (int i = 0; i < 16; i++)
        #pragma unroll
        for (int j = 0; j < 4; j++) oacc[i][j] = 0.f;

    const int nkt = 4 * qi + 4;
    for (int kt = 0; kt < nkt; kt++) {
        const int k0g = kt * 32;
        __syncthreads();
        // stage K,V tile (32 rows each, fp32 -> hi/lo, swizzled)
        for (int idx = tid; idx < 1024; idx += 256) {
            const int which = idx >> 9;            // 0: K, 1: V
            const int rem = idx & 511;
            const int row = rem >> 4, chunk = rem & 15;
            const float* src = (which ? Vb : Kb) + (size_t)(k0g + row) * DKH + chunk * 8;
            float4 a = *(const float4*)src;
            float4 b = *(const float4*)(src + 4);
            uint4 hi, lo;
            split8(a, b, hi, lo);
            const uint32_t off = (uint32_t)(row * 256) + (uint32_t)(((chunk ^ (row & 7)) << 4));
            const uint32_t hB = which ? VH_B : KH_B;
            const uint32_t lB = which ? VL_B : KL_B;
            *(uint4*)(sbc + hB + off) = hi;
            *(uint4*)(sbc + lB + off) = lo;
        }
        __syncthreads();

        if (k0g <= rw0 + 15) {                 // warp-tile not fully masked
            float sacc[4][4];
            #pragma unroll
            for (int j = 0; j < 4; j++)
                #pragma unroll
                for (int d = 0; d < 4; d++) sacc[j][d] = 0.f;
            #pragma unroll
            for (int kk = 0; kk < 8; kk++) {
                uint32_t afh[4], afl[4];
                ldsm_x4(afh, sbase + swb(QH_B, qrow, qcolb + kk*16));
                ldsm_x4(afl, sbase + swb(QL_B, qrow, qcolb + kk*16));
                #pragma unroll
                for (int np = 0; np < 2; np++) {
                    uint32_t bh4[4], bl4[4];
                    ldsm_x4(bh4, sbase + swb(KH_B, krow_b + np*16, kcolb + kk*16));
                    ldsm_x4(bl4, sbase + swb(KL_B, krow_b + np*16, kcolb + kk*16));
                    mma16816(sacc[2*np],   afh, bh4);
                    mma16816(sacc[2*np],   afh, bl4);
                    mma16816(sacc[2*np],   afl, bh4);
                    mma16816(sacc[2*np+1], afh, bh4+2);
                    mma16816(sacc[2*np+1], afh, bl4+2);
                    mma16816(sacc[2*np+1], afl, bh4+2);
                }
            }
            if (k0g + 31 > rw0) {
                const int row0 = rw0 + rr, row1 = row0 + 8;
                #pragma unroll
                for (int j = 0; j < 4; j++) {
                    const int c0 = k0g + j*8 + cc2;
                    if (c0     > row0) sacc[j][0] = -1e30f;
                    if (c0 + 1 > row0) sacc[j][1] = -1e30f;
                    if (c0     > row1) sacc[j][2] = -1e30f;
                    if (c0 + 1 > row1) sacc[j][3] = -1e30f;
                }
            }
            float mt0 = -INFINITY, mt1 = -INFINITY;
            #pragma unroll
            for (int j = 0; j < 4; j++) {
                mt0 = fmaxf(mt0, fmaxf(sacc[j][0], sacc[j][1]));
                mt1 = fmaxf(mt1, fmaxf(sacc[j][2], sacc[j][3]));
            }
            mt0 = fmaxf(mt0, __shfl_xor_sync(0xffffffffu, mt0, 1));
            mt0 = fmaxf(mt0, __shfl_xor_sync(0xffffffffu, mt0, 2));
            mt1 = fmaxf(mt1, __shfl_xor_sync(0xffffffffu, mt1, 1));
            mt1 = fmaxf(mt1, __shfl_xor_sync(0xffffffffu, mt1, 2));
            const float mn0 = fmaxf(m0, mt0), mn1 = fmaxf(m1, mt1);
            const float al0 = __expf(m0 - mn0), al1 = __expf(m1 - mn1);
            m0 = mn0; m1 = mn1;
            float s0 = 0.f, s1 = 0.f;
            uint32_t pah[2][4], pal[2][4];
            #pragma unroll
            for (int j = 0; j < 4; j++) {
                const float p00 = __expf(sacc[j][0] - m0);
                const float p01 = __expf(sacc[j][1] - m0);
                const float p10 = __expf(sacc[j][2] - m1);
                const float p11 = __expf(sacc[j][3] - m1);
                s0 += p00 + p01; s1 += p10 + p11;
                __nv_bfloat16 h00, h01, h10, h11;
                const uint32_t ph0 = pack_hilo2(p00, p01, h00, h01);
                const uint32_t ph1 = pack_hilo2(p10, p11, h10, h11);
                __nv_bfloat16 tt0, tt1;
                const uint32_t pl0 = pack_hilo2(p00 - __bfloat162float(h00),
                                                p01 - __bfloat162float(h01), tt0, tt1);
                const uint32_t pl1 = pack_hilo2(p10 - __bfloat162float(h10),
                                                p11 - __bfloat162float(h11), tt0, tt1);
                const int t = j >> 1, u = (j & 1) * 2;
                pah[t][u]   = ph0; pah[t][u+1] = ph1;
                pal[t][u]   = pl0; pal[t][u+1] = pl1;
            }
            s0 += __shfl_xor_sync(0xffffffffu, s0, 1);
            s0 += __shfl_xor_sync(0xffffffffu, s0, 2);
            s1 += __shfl_xor_sync(0xffffffffu, s1, 1);
            s1 += __shfl_xor_sync(0xffffffffu, s1, 2);
            l0 = l0*al0 + s0; l1 = l1*al1 + s1;
            #pragma unroll
            for (int na = 0; na < 16; na++) {
                oacc[na][0] *= al0; oacc[na][1] *= al0;
                oacc[na][2] *= al1; oacc[na][3] *= al1;
            }
            #pragma unroll
            for (int t = 0; t < 2; t++) {
                #pragma unroll
                for (int np = 0; np < 8; np++) {
                    uint32_t vh4[4], vl4[4];
                    ldsm_x4_t(vh4, sbase + swb(VH_B, vrow_b + t*16, vcolb + np*16));
                    ldsm_x4_t(vl4, sbase + swb(VL_B, vrow_b + t*16, vcolb + np*16));
                    mma16816(oacc[2*np],   pah[t], vh4);
                    mma16816(oacc[2*np],   pah[t], vl4);
                    mma16816(oacc[2*np],   pal[t], vh4);
                    mma16816(oacc[2*np+1], pah[t], vh4+2);
                    mma16816(oacc[2*np+1], pah[t], vl4+2);
                    mma16816(oacc[2*np+1], pal[t], vh4+2);
                }
            }
        }
    }

    // ---- epilogue: fp32 ctx (proven path) ----
    const float inv0 = 1.f / l0, inv1 = 1.f / l1;
    const int brow = bh >> 4, hh = bh & 15;
    const int s0r = rw0 + rr, s1r = s0r + 8;
    float* d0 = g_ctx + ((size_t)(brow*SEQL + s0r))*DMODEL + hh*DKH + cc2;
    float* d1 = g_ctx + ((size_t)(brow*SEQL + s1r))*DMODEL + hh*DKH + cc2;
    #pragma unroll
    for (int na = 0; na < 16; na++) {
        *(float2*)(d0 + na*8) = make_float2(oacc[na][0]*inv0, oacc[na][1]*inv0);
        *(float2*)(d1 + na*8) = make_float2(oacc[na][2]*inv1, oacc[na][3]*inv1);
    }
}

// ---------------- launch ----------------
extern "C" void kernel_launch(void* const* d_in, const int* in_sizes, int n_in,
                              void* d_out, int out_size)
{
    (void)in_sizes; (void)n_in; (void)out_size;
    const float* x      = (const float*)d_in[0];
    const int*   tokpos = (const int*)d_in[1];
    const float* Wq     = (const float*)d_in[2];
    const float* Wk     = (const float*)d_in[3];
    const float* Wv     = (const float*)d_in[4];
    const float* Wo     = (const float*)d_in[5];
    float* out = (float*)d_out;

    init_tables_kernel<<<SEQL, 64>>>();

    const int n4x = MROWS * DMODEL / 4;
    const int n4w = DMODEL * DMODEL / 4;
    convert_hilo_kernel<<<n4x/256, 256>>>(x,  0, n4x);
    convert_hilo_kernel<<<n4w/256, 256>>>(Wq, 1, n4w);
    convert_hilo_kernel<<<n4w/256, 256>>>(Wk, 2, n4w);
    convert_hilo_kernel<<<n4w/256, 256>>>(Wv, 3, n4w);
    convert_hilo_kernel<<<n4w/256, 256>>>(Wo, 4, n4w);

    cudaFuncSetAttribute(ms_gemm_kernel, cudaFuncAttributeMaxDynamicSharedMemorySize, GEMM_SMEM);
    // fused QKV projection: one launch, grid.y = 3 * 64 row-blocks
    ms_gemm_kernel<<<dim3(DMODEL/128, 3*(MROWS/128)), 256, GEMM_SMEM>>>(nullptr, 9, tokpos);

    cudaFuncSetAttribute(mha_mma_kernel, cudaFuncAttributeMaxDynamicSharedMemorySize, ASM_BYTES);
    mha_mma_kernel<<<dim3(SEQL/128, BATCH*NHEADS), 256, ASM_BYTES>>>();

    convert_hilo_kernel<<<n4x/256, 256>>>(nullptr, 5, n4x);  // ctx -> xhi/xlo
    ms_gemm_kernel<<<dim3(DMODEL/128, MROWS/128), 256, GEMM_SMEM>>>(out, 0, nullptr);  // output proj
}

// round 16
// speedup vs baseline: 1.2599x; 1.1145x over previous
#include <cuda_runtime.h>
#include <cuda_bf16.h>
#include <math.h>
#include <stdint.h>

#define BATCH 4
#define SEQL 2048
#define DMODEL 2048
#define NHEADS 16
#define DKH 128
#define MROWS (BATCH*SEQL)   // 8192

// ---------------- scratch (static device globals; no allocs allowed) ----------------
static __device__ float g_Q[BATCH*NHEADS*SEQL*DKH];     // [B,H,S,dk] fp32
static __device__ float g_K[BATCH*NHEADS*SEQL*DKH];
static __device__ float g_V[BATCH*NHEADS*SEQL*DKH];
static __device__ float g_ctx[BATCH*SEQL*DMODEL];       // attention output fp32
static __device__ float g_cos[SEQL*(DKH/2)];
static __device__ float g_sin[SEQL*(DKH/2)];
// hi/lo bf16 split operands (x and ctx share g_xhi/g_xlo: x dead after QKV)
static __device__ __nv_bfloat16 g_xhi[MROWS*DMODEL];
static __device__ __nv_bfloat16 g_xlo[MROWS*DMODEL];
static __device__ __nv_bfloat16 g_wqhi[DMODEL*DMODEL];
static __device__ __nv_bfloat16 g_wqlo[DMODEL*DMODEL];
static __device__ __nv_bfloat16 g_wkhi[DMODEL*DMODEL];
static __device__ __nv_bfloat16 g_wklo[DMODEL*DMODEL];
static __device__ __nv_bfloat16 g_wvhi[DMODEL*DMODEL];
static __device__ __nv_bfloat16 g_wvlo[DMODEL*DMODEL];
static __device__ __nv_bfloat16 g_wohi[DMODEL*DMODEL];
static __device__ __nv_bfloat16 g_wolo[DMODEL*DMODEL];

// ---------------- helpers ----------------
__device__ __forceinline__ uint32_t smem_u32(const void* p) {
    uint32_t a;
    asm("{ .reg .u64 t; cvta.to.shared.u64 t, %1; cvt.u32.u64 %0, t; }" : "=r"(a) : "l"(p));
    return a;
}
__device__ __forceinline__ void ldsm_x4(uint32_t* r, uint32_t addr) {
    asm volatile("ldmatrix.sync.aligned.m8n8.x4.shared.b16 {%0,%1,%2,%3}, [%4];"
        : "=r"(r[0]), "=r"(r[1]), "=r"(r[2]), "=r"(r[3]) : "r"(addr));
}
__device__ __forceinline__ void ldsm_x4_t(uint32_t* r, uint32_t addr) {
    asm volatile("ldmatrix.sync.aligned.m8n8.x4.trans.shared.b16 {%0,%1,%2,%3}, [%4];"
        : "=r"(r[0]), "=r"(r[1]), "=r"(r[2]), "=r"(r[3]) : "r"(addr));
}
__device__ __forceinline__ void ldsm_x2(uint32_t* r, uint32_t addr) {
    asm volatile("ldmatrix.sync.aligned.m8n8.x2.shared.b16 {%0,%1}, [%2];"
        : "=r"(r[0]), "=r"(r[1]) : "r"(addr));
}
__device__ __forceinline__ void mma16816(float* d, const uint32_t* a, const uint32_t* b) {
    asm volatile("mma.sync.aligned.m16n8k16.row.col.f32.bf16.bf16.f32 "
        "{%0,%1,%2,%3}, {%4,%5,%6,%7}, {%8,%9}, {%0,%1,%2,%3};"
        : "+f"(d[0]), "+f"(d[1]), "+f"(d[2]), "+f"(d[3])
        : "r"(a[0]), "r"(a[1]), "r"(a[2]), "r"(a[3]), "r"(b[0]), "r"(b[1]));
}
__device__ __forceinline__ uint32_t pack_hilo2(float x, float y,
                                               __nv_bfloat16& hx, __nv_bfloat16& hy) {
    hx = __float2bfloat16(x); hy = __float2bfloat16(y);
    __nv_bfloat162 p = __halves2bfloat162(hx, hy);
    return *(uint32_t*)&p;
}
__device__ __forceinline__ void split8(float4 a, float4 b, uint4& hi, uint4& lo) {
    float f[8] = {a.x, a.y, a.z, a.w, b.x, b.y, b.z, b.w};
    uint32_t hw[4], lw[4];
    #pragma unroll
    for (int i = 0; i < 4; i++) {
        __nv_bfloat16 h1, h2;
        hw[i] = pack_hilo2(f[2*i], f[2*i+1], h1, h2);
        __nv_bfloat16 t1, t2;
        lw[i] = pack_hilo2(f[2*i]   - __bfloat162float(h1),
                           f[2*i+1] - __bfloat162float(h2), t1, t2);
    }
    hi = make_uint4(hw[0], hw[1], hw[2], hw[3]);
    lo = make_uint4(lw[0], lw[1], lw[2], lw[3]);
}
__device__ __forceinline__ uint32_t swb(uint32_t regionB, int row, int col) {
    return regionB + (uint32_t)(row * 256) + (uint32_t)(((((col) >> 3) ^ (row & 7)) << 4));
}

// ---------------- RoPE table init ----------------
__global__ void init_tables_kernel()
{
    int t = blockIdx.x;
    int i = threadIdx.x;
    double freq = exp(-(double)i * (log(10000.0) / 64.0));
    float ang = (float)t * (float)freq;
    g_cos[t*64 + i] = (float)cos((double)ang);
    g_sin[t*64 + i] = (float)sin((double)ang);
}

// ---------------- fp32 -> (hi, lo) bf16 split ----------------
__global__ void convert_hilo_kernel(const float* __restrict__ src, int which, int n4)
{
    int idx = blockIdx.x * blockDim.x + threadIdx.x;
    if (idx >= n4) return;
    const float* s = src ? src : g_ctx;
    __nv_bfloat16 *hi, *lo;
    switch (which) {
        case 1: hi = g_wqhi; lo = g_wqlo; break;
        case 2: hi = g_wkhi; lo = g_wklo; break;
        case 3: hi = g_wvhi; lo = g_wvlo; break;
        case 4: hi = g_wohi; lo = g_wolo; break;
        default: hi = g_xhi; lo = g_xlo; break;   // 0 and 5
    }
    float4 v = ((const float4*)s)[idx];
    __nv_bfloat16 h0 = __float2bfloat16(v.x);
    __nv_bfloat16 h1 = __float2bfloat16(v.y);
    __nv_bfloat16 h2 = __float2bfloat16(v.z);
    __nv_bfloat16 h3 = __float2bfloat16(v.w);
    __nv_bfloat16 l0 = __float2bfloat16(v.x - __bfloat162float(h0));
    __nv_bfloat16 l1 = __float2bfloat16(v.y - __bfloat162float(h1));
    __nv_bfloat16 l2 = __float2bfloat16(v.z - __bfloat162float(h2));
    __nv_bfloat16 l3 = __float2bfloat16(v.w - __bfloat162float(h3));
    __nv_bfloat162* hp = (__nv_bfloat162*)hi;
    __nv_bfloat162* lp = (__nv_bfloat162*)lo;
    hp[2*idx]   = __halves2bfloat162(h0, h1);
    hp[2*idx+1] = __halves2bfloat162(h2, h3);
    lp[2*idx]   = __halves2bfloat162(l0, l1);
    lp[2*idx+1] = __halves2bfloat162(l2, l3);
}

// ---------------- mma.sync bf16 hi/lo GEMM (R15-proven: KC=64, dynamic smem) ----------------
// mode 9: fused QKV — one launch, grid.y in [0,192): operator = y>>6 (0:Q,1:K,2:V),
//         row-block = y&63. fp32 epilogues (proven path).
// mode 0: A=ctx(xhi/xlo), write Cp fp32 row-major
#define KC 64
#define STR 72                      // 64 + 8 pad (bf16)
#define REGN (128*STR)              // elements per region
#define GEMM_SMEM (4*REGN*2)        // 73728 bytes dynamic

__global__ void __launch_bounds__(256, 2) ms_gemm_kernel(float* __restrict__ Cp, int mode,
                                                         const int* __restrict__ tokpos)
{
    extern __shared__ __nv_bfloat16 dsm[];
    __nv_bfloat16* sAh = dsm;
    __nv_bfloat16* sAl = dsm + REGN;
    __nv_bfloat16* sBh = dsm + 2*REGN;
    __nv_bfloat16* sBl = dsm + 3*REGN;

    int emode, bmBlk;
    if (mode == 9) { emode = 1 + (int)(blockIdx.y >> 6); bmBlk = (int)(blockIdx.y & 63); }
    else           { emode = mode;                        bmBlk = (int)blockIdx.y; }

    const int tid = threadIdx.x;
    const int wid = tid >> 5, lane = tid & 31;
    const int wm = wid >> 2, wn = wid & 3;
    const int bm = bmBlk * 128, bn = blockIdx.x * 128;

    const __nv_bfloat16 *Ah = g_xhi, *Al = g_xlo, *Bh, *Bl;
    if (emode == 0)      { Bh = g_wohi; Bl = g_wolo; }
    else if (emode == 1) { Bh = g_wqhi; Bl = g_wqlo; }
    else if (emode == 2) { Bh = g_wkhi; Bl = g_wklo; }
    else                 { Bh = g_wvhi; Bl = g_wvlo; }

    float acc[4][4][4];
    #pragma unroll
    for (int i = 0; i < 4; i++)
        #pragma unroll
        for (int j = 0; j < 4; j++)
            #pragma unroll
            for (int d = 0; d < 4; d++) acc[i][j][d] = 0.f;

    const uint32_t sah = smem_u32(sAh), sal = smem_u32(sAl);
    const uint32_t sbh = smem_u32(sBh), sbl = smem_u32(sBl);
    const int r8 = lane & 7, sel = lane >> 3;
    const int a_row_part = wm*64 + r8 + (sel & 1) * 8;
    const int a_col_part = (sel >> 1) * 8;
    const int b_row_part = wn*32 + r8;
    const int b_col_part = (sel & 1) * 8;

    for (int c = 0; c < 32; c++) {
        const int k0 = c * KC;
        __syncthreads();
        #pragma unroll
        for (int t = 0; t < 4; t++) {
            const int slot = tid + t*256;      // 0..1023
            const int row = slot >> 3, seg = slot & 7;
            const int so = row*STR + seg*8;
            const size_t ga = (size_t)(bm + row) * DMODEL + k0 + seg*8;
            const size_t gb = (size_t)(bn + row) * DMODEL + k0 + seg*8;
            *(uint4*)(sAh + so) = *(const uint4*)(Ah + ga);
            *(uint4*)(sAl + so) = *(const uint4*)(Al + ga);
            *(uint4*)(sBh + so) = *(const uint4*)(Bh + gb);
            *(uint4*)(sBl + so) = *(const uint4*)(Bl + gb);
        }
        __syncthreads();
        #pragma unroll
        for (int kk = 0; kk < 4; kk++) {
            const int kof = kk * 16;
            uint32_t bfh[4][2], bfl[4][2];
            #pragma unroll
            for (int an = 0; an < 4; an++) {
                const uint32_t ba = 2u * (uint32_t)((b_row_part + an*8)*STR + b_col_part + kof);
                ldsm_x2(bfh[an], sbh + ba);
                ldsm_x2(bfl[an], sbl + ba);
            }
            #pragma unroll
            for (int am = 0; am < 4; am++) {
                const uint32_t aa = 2u * (uint32_t)((a_row_part + am*16)*STR + a_col_part + kof);
                uint32_t afh[4], afl[4];
                ldsm_x4(afh, sah + aa);
                ldsm_x4(afl, sal + aa);
                #pragma unroll
                for (int an = 0; an < 4; an++) {
                    mma16816(acc[am][an], afh, bfh[an]);
                    mma16816(acc[am][an], afh, bfl[an]);
                    mma16816(acc[am][an], afl, bfh[an]);
                }
            }
        }
    }

    const int rr = lane >> 2;
    const int cc = (lane & 3) * 2;
    if (emode == 0) {
        #pragma unroll
        for (int am = 0; am < 4; am++)
            #pragma unroll
            for (int h2 = 0; h2 < 2; h2++) {
                const int m = bm + wm*64 + am*16 + rr + h2*8;
                #pragma unroll
                for (int an = 0; an < 4; an++) {
                    const int n = bn + wn*32 + an*8 + cc;
                    *(float2*)(Cp + (size_t)m * DMODEL + n) =
                        make_float2(acc[am][an][h2*2], acc[am][an][h2*2+1]);
                }
            }
    } else {
        const int h = bn >> 7;
        float* base = (emode == 1) ? g_Q : ((emode == 2) ? g_K : g_V);
        const float qscale = 0.08838834764831845f;  // 1/sqrt(128)
        #pragma unroll
        for (int am = 0; am < 4; am++)
            #pragma unroll
            for (int h2 = 0; h2 < 2; h2++) {
                const int m = bm + wm*64 + am*16 + rr + h2*8;
                const int b = m >> 11;
                const int s = m & (SEQL - 1);
                float* drow = base + ((size_t)(b * NHEADS + h) * SEQL + s) * DKH;
                if (emode == 3) {
                    #pragma unroll
                    for (int an = 0; an < 4; an++) {
                        const int d = wn*32 + an*8 + cc;
                        *(float2*)(drow + d) =
                            make_float2(acc[am][an][h2*2], acc[am][an][h2*2+1]);
                    }
                } else {
                    const int p = tokpos[s];
                    #pragma unroll
                    for (int an = 0; an < 4; an++) {
                        const int d = wn*32 + an*8 + cc;
                        const int pi = d >> 1;
                        const float co = g_cos[p*64 + pi];
                        const float si = g_sin[p*64 + pi];
                        const float x1 = acc[am][an][h2*2];
                        const float x2 = acc[am][an][h2*2+1];
                        float r1 = co*x1 - si*x2;
                        float r2 = si*x1 + co*x2;
                        if (emode == 1) { r1 *= qscale; r2 *= qscale; }
                        *(float2*)(drow + d) = make_float2(r1, r2);
                    }
                }
            }
    }
}

// ---------------- flash attention via mma.sync bf16 hi/lo (R13 core; 2 CTAs/SM) ----------------
#define QH_B 0u
#define QL_B 32768u
#define KH_B 65536u
#define KL_B 73728u
#define VH_B 81920u
#define VL_B 90112u
#define ASM_BYTES 98304

__global__ void __launch_bounds__(256, 2) mha_mma_kernel()
{
    extern __shared__ char sbc[];
    const uint32_t sbase = smem_u32(sbc);
    const int tid = threadIdx.x, wid = tid >> 5, lane = tid & 31;
    const int qi = (int)gridDim.x - 1 - (int)blockIdx.x;   // big q-tiles first
    const int bh = blockIdx.y;
    const int q0 = qi * 128;
    const size_t boff = (size_t)bh * SEQL * DKH;
    const float* Qb = g_Q + boff;
    const float* Kb = g_K + boff;
    const float* Vb = g_V + boff;

    // stage Q (fp32 -> hi/lo, swizzled)
    for (int idx = tid; idx < 128*16; idx += 256) {
        const int row = idx >> 4, chunk = idx & 15;
        const float* src = Qb + (size_t)(q0 + row) * DKH + chunk * 8;
        float4 a = *(const float4*)src;
        float4 b = *(const float4*)(src + 4);
        uint4 hi, lo;
        split8(a, b, hi, lo);
        const uint32_t off = (uint32_t)(row * 256) + (uint32_t)(((chunk ^ (row & 7)) << 4));
        *(uint4*)(sbc + QH_B + off) = hi;
        *(uint4*)(sbc + QL_B + off) = lo;
    }

    const int r8 = lane & 7, sel = lane >> 3;
    const int qrow = wid*16 + r8 + ((sel & 1) << 3);
    const int qcolb = (sel >> 1) << 3;
    const int krow_b = r8 + ((sel >> 1) << 3);
    const int kcolb = (sel & 1) << 3;
    const int vrow_b = r8 + ((sel & 1) << 3);
    const int vcolb = (sel >> 1) << 3;

    const int rr = lane >> 2, cc2 = (lane & 3) * 2;
    const int rw0 = q0 + wid * 16;
    float m0 = -INFINITY, m1 = -INFINITY, l0 = 0.f, l1 = 0.f;
    float oacc[16][4];
    #pragma unroll
    for (int i = 0; i < 16; i++)
        #pragma unroll
        for (int j = 0; j < 4; j++) oacc[i][j] = 0.f;

    const int nkt = 4 * qi + 4;
    for (int kt = 0; kt < nkt; kt++) {
        const int k0g = kt * 32;
        __syncthreads();
        // stage K,V tile (32 rows each, fp32 -> hi/lo, swizzled)
        for (int idx = tid; idx < 1024; idx += 256) {
            const int which = idx >> 9;            // 0: K, 1: V
            const int rem = idx & 511;
            const int row = rem >> 4, chunk = rem & 15;
            const float* src = (which ? Vb : Kb) + (size_t)(k0g + row) * DKH + chunk * 8;
            float4 a = *(const float4*)src;
            float4 b = *(const float4*)(src + 4);
            uint4 hi, lo;
            split8(a, b, hi, lo);
            const uint32_t off = (uint32_t)(row * 256) + (uint32_t)(((chunk ^ (row & 7)) << 4));
            const uint32_t hB = which ? VH_B : KH_B;
            const uint32_t lB = which ? VL_B : KL_B;
            *(uint4*)(sbc + hB + off) = hi;
            *(uint4*)(sbc + lB + off) = lo;
        }
        __syncthreads();

        if (k0g <= rw0 + 15) {                 // warp-tile not fully masked
            float sacc[4][4];
            #pragma unroll
            for (int j = 0; j < 4; j++)
                #pragma unroll
                for (int d = 0; d < 4; d++) sacc[j][d] = 0.f;
            #pragma unroll
            for (int kk = 0; kk < 8; kk++) {
                uint32_t afh[4], afl[4];
                ldsm_x4(afh, sbase + swb(QH_B, qrow, qcolb + kk*16));
                ldsm_x4(afl, sbase + swb(QL_B, qrow, qcolb + kk*16));
                #pragma unroll
                for (int np = 0; np < 2; np++) {
                    uint32_t bh4[4], bl4[4];
                    ldsm_x4(bh4, sbase + swb(KH_B, krow_b + np*16, kcolb + kk*16));
                    ldsm_x4(bl4, sbase + swb(KL_B, krow_b + np*16, kcolb + kk*16));
                    mma16816(sacc[2*np],   afh, bh4);
                    mma16816(sacc[2*np],   afh, bl4);
                    mma16816(sacc[2*np],   afl, bh4);
                    mma16816(sacc[2*np+1], afh, bh4+2);
                    mma16816(sacc[2*np+1], afh, bl4+2);
                    mma16816(sacc[2*np+1], afl, bh4+2);
                }
            }
            if (k0g + 31 > rw0) {
                const int row0 = rw0 + rr, row1 = row0 + 8;
                #pragma unroll
                for (int j = 0; j < 4; j++) {
                    const int c0 = k0g + j*8 + cc2;
                    if (c0     > row0) sacc[j][0] = -1e30f;
                    if (c0 + 1 > row0) sacc[j][1] = -1e30f;
                    if (c0     > row1) sacc[j][2] = -1e30f;
                    if (c0 + 1 > row1) sacc[j][3] = -1e30f;
                }
            }
            float mt0 = -INFINITY, mt1 = -INFINITY;
            #pragma unroll
            for (int j = 0; j < 4; j++) {
                mt0 = fmaxf(mt0, fmaxf(sacc[j][0], sacc[j][1]));
                mt1 = fmaxf(mt1, fmaxf(sacc[j][2], sacc[j][3]));
            }
            mt0 = fmaxf(mt0, __shfl_xor_sync(0xffffffffu, mt0, 1));
            mt0 = fmaxf(mt0, __shfl_xor_sync(0xffffffffu, mt0, 2));
            mt1 = fmaxf(mt1, __shfl_xor_sync(0xffffffffu, mt1, 1));
            mt1 = fmaxf(mt1, __shfl_xor_sync(0xffffffffu, mt1, 2));
            const float mn0 = fmaxf(m0, mt0), mn1 = fmaxf(m1, mt1);
            const float al0 = __expf(m0 - mn0), al1 = __expf(m1 - mn1);
            m0 = mn0; m1 = mn1;
            float s0 = 0.f, s1 = 0.f;
            uint32_t pah[2][4], pal[2][4];
            #pragma unroll
            for (int j = 0; j < 4; j++) {
                const float p00 = __expf(sacc[j][0] - m0);
                const float p01 = __expf(sacc[j][1] - m0);
                const float p10 = __expf(sacc[j][2] - m1);
                const float p11 = __expf(sacc[j][3] - m1);
                s0 += p00 + p01; s1 += p10 + p11;
                __nv_bfloat16 h00, h01, h10, h11;
                const uint32_t ph0 = pack_hilo2(p00, p01, h00, h01);
                const uint32_t ph1 = pack_hilo2(p10, p11, h10, h11);
                __nv_bfloat16 tt0, tt1;
                const uint32_t pl0 = pack_hilo2(p00 - __bfloat162float(h00),
                                                p01 - __bfloat162float(h01), tt0, tt1);
                const uint32_t pl1 = pack_hilo2(p10 - __bfloat162float(h10),
                                                p11 - __bfloat162float(h11), tt0, tt1);
                const int t = j >> 1, u = (j & 1) * 2;
                pah[t][u]   = ph0; pah[t][u+1] = ph1;
                pal[t][u]   = pl0; pal[t][u+1] = pl1;
            }
            s0 += __shfl_xor_sync(0xffffffffu, s0, 1);
            s0 += __shfl_xor_sync(0xffffffffu, s0, 2);
            s1 += __shfl_xor_sync(0xffffffffu, s1, 1);
            s1 += __shfl_xor_sync(0xffffffffu, s1, 2);
            l0 = l0*al0 + s0; l1 = l1*al1 + s1;
            #pragma unroll
            for (int na = 0; na < 16; na++) {
                oacc[na][0] *= al0; oacc[na][1] *= al0;
                oacc[na][2] *= al1; oacc[na][3] *= al1;
            }
            #pragma unroll
            for (int t = 0; t < 2; t++) {
                #pragma unroll
                for (int np = 0; np < 8; np++) {
                    uint32_t vh4[4], vl4[4];
                    ldsm_x4_t(vh4, sbase + swb(VH_B, vrow_b + t*16, vcolb + np*16));
                    ldsm_x4_t(vl4, sbase + swb(VL_B, vrow_b + t*16, vcolb + np*16));
                    mma16816(oacc[2*np],   pah[t], vh4);
                    mma16816(oacc[2*np],   pah[t], vl4);
                    mma16816(oacc[2*np],   pal[t], vh4);
                    mma16816(oacc[2*np+1], pah[t], vh4+2);
                    mma16816(oacc[2*np+1], pah[t], vl4+2);
                    mma16816(oacc[2*np+1], pal[t], vh4+2);
                }
            }
        }
    }

    // ---- epilogue: fp32 ctx (proven path) ----
    const float inv0 = 1.f / l0, inv1 = 1.f / l1;
    const int brow = bh >> 4, hh = bh & 15;
    const int s0r = rw0 + rr, s1r = s0r + 8;
    float* d0 = g_ctx + ((size_t)(brow*SEQL + s0r))*DMODEL + hh*DKH + cc2;
    float* d1 = g_ctx + ((size_t)(brow*SEQL + s1r))*DMODEL + hh*DKH + cc2;
    #pragma unroll
    for (int na = 0; na < 16; na++) {
        *(float2*)(d0 + na*8) = make_float2(oacc[na][0]*inv0, oacc[na][1]*inv0);
        *(float2*)(d1 + na*8) = make_float2(oacc[na][2]*inv1, oacc[na][3]*inv1);
    }
}

// ---------------- launch ----------------
extern "C" void kernel_launch(void* const* d_in, const int* in_sizes, int n_in,
                              void* d_out, int out_size)
{
    (void)in_sizes; (void)n_in; (void)out_size;
    const float* x      = (const float*)d_in[0];
    const int*   tokpos = (const int*)d_in[1];
    const float* Wq     = (const float*)d_in[2];
    const float* Wk     = (const float*)d_in[3];
    const float* Wv     = (const float*)d_in[4];
    const float* Wo     = (const float*)d_in[5];
    float* out = (float*)d_out;

    init_tables_kernel<<<SEQL, 64>>>();

    const int n4x = MROWS * DMODEL / 4;
    const int n4w = DMODEL * DMODEL / 4;
    convert_hilo_kernel<<<n4x/256, 256>>>(x,  0, n4x);
    convert_hilo_kernel<<<n4w/256, 256>>>(Wq, 1, n4w);
    convert_hilo_kernel<<<n4w/256, 256>>>(Wk, 2, n4w);
    convert_hilo_kernel<<<n4w/256, 256>>>(Wv, 3, n4w);
    convert_hilo_kernel<<<n4w/256, 256>>>(Wo, 4, n4w);

    cudaFuncSetAttribute(ms_gemm_kernel, cudaFuncAttributeMaxDynamicSharedMemorySize, GEMM_SMEM);
    // fused QKV projection: one launch, grid.y = 3 * 64 row-blocks
    ms_gemm_kernel<<<dim3(DMODEL/128, 3*(MROWS/128)), 256, GEMM_SMEM>>>(nullptr, 9, tokpos);

    cudaFuncSetAttribute(mha_mma_kernel, cudaFuncAttributeMaxDynamicSharedMemorySize, ASM_BYTES);
    mha_mma_kernel<<<dim3(SEQL/128, BATCH*NHEADS), 256, ASM_BYTES>>>();

    convert_hilo_kernel<<<n4x/256, 256>>>(nullptr, 5, n4x);  // ctx -> xhi/xlo
    ms_gemm_kernel<<<dim3(DMODEL/128, MROWS/128), 256, GEMM_SMEM>>>(out, 0, nullptr);  // output proj
}